// round 5
// baseline (speedup 1.0000x reference)
#include <cuda_runtime.h>
#include <cuda_bf16.h>
#include <cstdint>

// Problem constants (verified against reference: N=50000, E=800000, D=HID=128, K=3)
#define MAXN 50000
#define MAXE 800000
#define D 128

// ---------------- scratch (no allocs allowed -> __device__ globals) ----------------
__device__ float g_T1[MAXN * D];   // Tx1 = prop(H)
__device__ float g_P [MAXN * D];   // P   = prop(Tx1)
__device__ float g_Ha[MAXN * D];   // layer outputs (ping)
__device__ float g_Hb[MAXN * D];   // layer outputs (pong)
__device__ float g_w [MAXE];       // edge weights
__device__ float g_deg [MAXN];
__device__ float g_dinv[MAXN];
__device__ float g_Wc[3 * D * D];  // combined weight [384][128]: {W0-W2, W1, 2*W2}

// ---------------- small kernels ----------------
__global__ void zero_kernel(float* __restrict__ p, int n4) {
    int i = blockIdx.x * blockDim.x + threadIdx.x;
    if (i < n4) reinterpret_cast<float4*>(p)[i] = make_float4(0.f, 0.f, 0.f, 0.f);
}

__global__ void deg_kernel(const int* __restrict__ row, const int* __restrict__ col,
                           float* __restrict__ deg, int E) {
    int e = blockIdx.x * blockDim.x + threadIdx.x;
    if (e < E) {
        int r = row[e], c = col[e];
        if (r != c) atomicAdd(&deg[r], 1.0f);
    }
}

__global__ void dinv_kernel(const float* __restrict__ deg, float* __restrict__ dinv, int n) {
    int i = blockIdx.x * blockDim.x + threadIdx.x;
    if (i < n) {
        float d = deg[i];
        dinv[i] = (d > 0.f) ? rsqrtf(fmaxf(d, 1.f)) : 0.f;
    }
}

__global__ void wedge_kernel(const int* __restrict__ row, const int* __restrict__ col,
                             const float* __restrict__ dinv, float* __restrict__ w, int E) {
    int e = blockIdx.x * blockDim.x + threadIdx.x;
    if (e < E) {
        int r = row[e], c = col[e];
        w[e] = (r != c) ? (-dinv[r] * dinv[c]) : 0.f;
    }
}

// Combined weight: Wc[0:128]=W0-W2, Wc[128:256]=W1, Wc[256:384]=2*W2
// (folds Tx2 = 2*prop(Tx1) - Tx0 into the GEMM)
__global__ void prep_w_kernel(const float* __restrict__ W, float* __restrict__ Wc) {
    int idx = blockIdx.x * blockDim.x + threadIdx.x;   // over 128*128 (i,j)
    if (idx < D * D) {
        float w0 = W[idx];
        float w1 = W[D * D + idx];
        float w2 = W[2 * D * D + idx];
        Wc[idx]             = w0 - w2;
        Wc[D * D + idx]     = w1;
        Wc[2 * D * D + idx] = 2.f * w2;
    }
}

// ---------------- sparse propagation: dst[row] += w * src[col] ----------------
// One warp per edge; lane covers 4 contiguous features (float4 gather + v4 RED).
__global__ __launch_bounds__(256) void prop_kernel(
    const float* __restrict__ src, float* __restrict__ dst,
    const int* __restrict__ row, const int* __restrict__ col,
    const float* __restrict__ w, int E)
{
    int gw   = (blockIdx.x * blockDim.x + threadIdx.x) >> 5;
    int lane = threadIdx.x & 31;
    if (gw >= E) return;
    int   r  = __ldg(row + gw);
    int   c  = __ldg(col + gw);
    float we = __ldg(w + gw);
    if (we == 0.f) return;  // self-loops (warp-uniform branch)

    float4 v = *reinterpret_cast<const float4*>(src + (size_t)c * D + lane * 4);
    v.x *= we; v.y *= we; v.z *= we; v.w *= we;
    float* d = dst + (size_t)r * D + lane * 4;
    asm volatile("red.global.add.v4.f32 [%0], {%1, %2, %3, %4};"
                 :: "l"(d), "f"(v.x), "f"(v.y), "f"(v.z), "f"(v.w)
                 : "memory");
}

// ---------------- fused triple GEMM + bias + ReLU ----------------
// OUT[n,:] = relu( H[n]@Wc[0:128] + T1[n]@Wc[128:256] + P[n]@Wc[256:384] + b )
// Tile: 64 rows x 128 cols per block, 256 threads, 4x8 per thread, BK=16, K=384.
#define BM 64
#define BN 128
#define BK 16

__global__ __launch_bounds__(256) void gemm3_kernel(
    const float* __restrict__ A0, const float* __restrict__ A1, const float* __restrict__ A2,
    const float* __restrict__ Wc, const float* __restrict__ bias,
    float* __restrict__ out, int nrows)
{
    __shared__ float As[BK][BM];   // transposed A tile
    __shared__ float Bs[BK][BN];

    const int tid  = threadIdx.x;
    const int tx   = tid & 15;        // 0..15 -> col group (8 cols)
    const int ty   = tid >> 4;        // 0..15 -> row group (4 rows)
    const int row0 = blockIdx.x * BM;

    // A-tile load mapping: 64 rows x 16 k -> one float4 per thread
    const int a_row = tid >> 2;          // 0..63
    const int a_k   = (tid & 3) << 2;    // 0,4,8,12
    // B-tile load mapping: 16 k x 128 cols -> two float4 per thread
    const int b_k = tid >> 5;            // 0..7
    const int b_c = (tid & 31) << 2;     // 0..124

    float acc[4][8];
#pragma unroll
    for (int i = 0; i < 4; i++)
#pragma unroll
        for (int j = 0; j < 8; j++) acc[i][j] = 0.f;

    const int  grow  = row0 + a_row;
    const bool valid = (grow < nrows);

    for (int kc = 0; kc < 24; ++kc) {   // 24 chunks of 16 = K=384
        const int which = kc >> 3;      // 0,1,2 -> A0,A1,A2 (128 each)
        const float* A  = (which == 0) ? A0 : (which == 1) ? A1 : A2;
        const int ksrc  = (kc & 7) * BK;

        float4 av = make_float4(0.f, 0.f, 0.f, 0.f);
        if (valid)
            av = *reinterpret_cast<const float4*>(A + (size_t)grow * D + ksrc + a_k);
        As[a_k + 0][a_row] = av.x;
        As[a_k + 1][a_row] = av.y;
        As[a_k + 2][a_row] = av.z;
        As[a_k + 3][a_row] = av.w;

        const float* Wrow = Wc + (size_t)(kc * BK) * D;
        *reinterpret_cast<float4*>(&Bs[b_k][b_c]) =
            *reinterpret_cast<const float4*>(Wrow + (size_t)b_k * D + b_c);
        *reinterpret_cast<float4*>(&Bs[b_k + 8][b_c]) =
            *reinterpret_cast<const float4*>(Wrow + (size_t)(b_k + 8) * D + b_c);

        __syncthreads();

#pragma unroll
        for (int kk = 0; kk < BK; kk++) {
            float4 a  = *reinterpret_cast<const float4*>(&As[kk][ty * 4]);
            float4 b0 = *reinterpret_cast<const float4*>(&Bs[kk][tx * 8]);
            float4 b1 = *reinterpret_cast<const float4*>(&Bs[kk][tx * 8 + 4]);
            float av4[4] = {a.x, a.y, a.z, a.w};
            float bv[8]  = {b0.x, b0.y, b0.z, b0.w, b1.x, b1.y, b1.z, b1.w};
#pragma unroll
            for (int i = 0; i < 4; i++)
#pragma unroll
                for (int j = 0; j < 8; j++)
                    acc[i][j] = fmaf(av4[i], bv[j], acc[i][j]);
        }
        __syncthreads();
    }

    // epilogue: + bias, ReLU, store
    float b0 = bias[tx * 8 + 0], b1 = bias[tx * 8 + 1], b2 = bias[tx * 8 + 2], b3 = bias[tx * 8 + 3];
    float b4 = bias[tx * 8 + 4], b5 = bias[tx * 8 + 5], b6 = bias[tx * 8 + 6], b7 = bias[tx * 8 + 7];
#pragma unroll
    for (int i = 0; i < 4; i++) {
        int r = row0 + ty * 4 + i;
        if (r >= nrows) continue;
        float4 v0, v1;
        v0.x = fmaxf(acc[i][0] + b0, 0.f);
        v0.y = fmaxf(acc[i][1] + b1, 0.f);
        v0.z = fmaxf(acc[i][2] + b2, 0.f);
        v0.w = fmaxf(acc[i][3] + b3, 0.f);
        v1.x = fmaxf(acc[i][4] + b4, 0.f);
        v1.y = fmaxf(acc[i][5] + b5, 0.f);
        v1.z = fmaxf(acc[i][6] + b6, 0.f);
        v1.w = fmaxf(acc[i][7] + b7, 0.f);
        *reinterpret_cast<float4*>(out + (size_t)r * D + tx * 8)     = v0;
        *reinterpret_cast<float4*>(out + (size_t)r * D + tx * 8 + 4) = v1;
    }
}

// ---------------- host-side orchestration ----------------
static inline int ceil_div(int a, int b) { return (a + b - 1) / b; }

extern "C" void kernel_launch(void* const* d_in, const int* in_sizes, int n_in,
                              void* d_out, int out_size)
{
    const float* x  = (const float*)d_in[0];
    const int*   ei = (const int*)  d_in[1];
    const float* W1 = (const float*)d_in[2];
    const float* b1 = (const float*)d_in[3];
    const float* W2 = (const float*)d_in[4];
    const float* b2 = (const float*)d_in[5];
    const float* W3 = (const float*)d_in[6];
    const float* b3 = (const float*)d_in[7];
    float* out = (float*)d_out;

    const int N = in_sizes[0] / D;
    const int E = in_sizes[1] / 2;
    const int* row = ei;
    const int* col = ei + E;

    // resolve device-global scratch addresses (host API, not a stream op; capture-safe)
    float *T1, *P, *Ha, *Hb, *w, *deg, *dinv, *Wc;
    cudaGetSymbolAddress((void**)&T1,   g_T1);
    cudaGetSymbolAddress((void**)&P,    g_P);
    cudaGetSymbolAddress((void**)&Ha,   g_Ha);
    cudaGetSymbolAddress((void**)&Hb,   g_Hb);
    cudaGetSymbolAddress((void**)&w,    g_w);
    cudaGetSymbolAddress((void**)&deg,  g_deg);
    cudaGetSymbolAddress((void**)&dinv, g_dinv);
    cudaGetSymbolAddress((void**)&Wc,   g_Wc);

    const int nd4   = (N * D) / 4;           // float4 count of a feature buffer
    const int zgrid = ceil_div(nd4, 256);
    const int egrid = ceil_div(E, 256);
    const int pgrid = ceil_div(E * 32, 256); // one warp per edge
    const int ggrid = ceil_div(N, BM);

    // edge weights: deg -> dinv -> w
    zero_kernel<<<ceil_div(N / 4 + 1, 256), 256>>>(deg, N / 4);
    deg_kernel<<<egrid, 256>>>(row, col, deg, E);
    dinv_kernel<<<ceil_div(N, 256), 256>>>(deg, dinv, N);
    wedge_kernel<<<egrid, 256>>>(row, col, dinv, w, E);

    // ---- layer 1: in = x, out = Ha ----
    zero_kernel<<<zgrid, 256>>>(T1, nd4);
    prop_kernel<<<pgrid, 256>>>(x, T1, row, col, w, E);
    zero_kernel<<<zgrid, 256>>>(P, nd4);
    prop_kernel<<<pgrid, 256>>>(T1, P, row, col, w, E);
    prep_w_kernel<<<ceil_div(D * D, 256), 256>>>(W1, Wc);
    gemm3_kernel<<<ggrid, 256>>>(x, T1, P, Wc, b1, Ha, N);

    // ---- layer 2: in = Ha, out = Hb ----
    zero_kernel<<<zgrid, 256>>>(T1, nd4);
    prop_kernel<<<pgrid, 256>>>(Ha, T1, row, col, w, E);
    zero_kernel<<<zgrid, 256>>>(P, nd4);
    prop_kernel<<<pgrid, 256>>>(T1, P, row, col, w, E);
    prep_w_kernel<<<ceil_div(D * D, 256), 256>>>(W2, Wc);
    gemm3_kernel<<<ggrid, 256>>>(Ha, T1, P, Wc, b2, Hb, N);

    // ---- layer 3: in = Hb, out = d_out ----
    zero_kernel<<<zgrid, 256>>>(T1, nd4);
    prop_kernel<<<pgrid, 256>>>(Hb, T1, row, col, w, E);
    zero_kernel<<<zgrid, 256>>>(P, nd4);
    prop_kernel<<<pgrid, 256>>>(T1, P, row, col, w, E);
    prep_w_kernel<<<ceil_div(D * D, 256), 256>>>(W3, Wc);
    gemm3_kernel<<<ggrid, 256>>>(Hb, T1, P, Wc, b3, out, N);
}

// round 6
// speedup vs baseline: 1.4954x; 1.4954x over previous
#include <cuda_runtime.h>
#include <cuda_bf16.h>
#include <cstdint>

// Problem constants (N=50000, E=800000, D=HID=128, K=3)
#define MAXN 50000
#define MAXE 800000
#define D 128

// ---------------- scratch (no allocs allowed -> __device__ globals) ----------------
__device__ float g_T1[MAXN * D];     // Tx1 = prop(H)
__device__ float g_P [MAXN * D];     // P   = prop(Tx1)
__device__ float g_Ha[MAXN * D];     // layer outputs (ping)
__device__ float g_Hb[MAXN * D];     // layer outputs (pong)
__device__ float g_Wc[3 * D * D];    // combined weight [384][128]: {W0-W2, W1, 2*W2}
__device__ float g_dinv[MAXN];
__device__ int   g_cnt   [MAXN];     // per-row non-self edge count (= degree)
__device__ int   g_rowptr[MAXN + 1];
__device__ int   g_cur   [MAXN];     // scatter cursors
__device__ int   g_cidx  [MAXE];     // CSR col indices
__device__ float g_cw    [MAXE];     // CSR edge weights

// ---------------- CSR build ----------------
__global__ void zero_int_kernel(int* __restrict__ p, int n) {
    int i = blockIdx.x * blockDim.x + threadIdx.x;
    if (i < n) p[i] = 0;
}

__global__ void hist_kernel(const int* __restrict__ row, const int* __restrict__ col,
                            int* __restrict__ cnt, int E) {
    int e = blockIdx.x * blockDim.x + threadIdx.x;
    if (e < E) {
        int r = row[e], c = col[e];
        if (r != c) atomicAdd(&cnt[r], 1);
    }
}

__global__ void dinv_kernel(const int* __restrict__ cnt, float* __restrict__ dinv, int n) {
    int i = blockIdx.x * blockDim.x + threadIdx.x;
    if (i < n) {
        int d = cnt[i];
        dinv[i] = (d > 0) ? rsqrtf((float)d) : 0.f;
    }
}

// Single-block exclusive scan: cnt[0..N) -> rowptr[0..N], cur[0..N)
__global__ __launch_bounds__(1024) void scan_kernel(
    const int* __restrict__ cnt, int* __restrict__ rowptr, int* __restrict__ cur, int N)
{
    __shared__ int ssum[1024];
    const int t = threadIdx.x;
    const int chunk = (N + 1023) / 1024;
    const int lo = t * chunk;
    const int hi = min(lo + chunk, N);

    int s = 0;
    for (int i = lo; i < hi; i++) s += cnt[i];
    ssum[t] = s;
    __syncthreads();

    // Hillis-Steele inclusive scan over block sums
    for (int off = 1; off < 1024; off <<= 1) {
        int v = ssum[t];
        int u = (t >= off) ? ssum[t - off] : 0;
        __syncthreads();
        ssum[t] = v + u;
        __syncthreads();
    }

    int run = (t > 0) ? ssum[t - 1] : 0;
    for (int i = lo; i < hi; i++) {
        rowptr[i] = run;
        cur[i]    = run;
        run += cnt[i];
    }
    if (t == 1023) rowptr[N] = ssum[1023];
}

// Scatter edges into CSR, fusing edge-weight computation. Order within a row is
// nondeterministic (atomic cursor) but consistent for all 6 props in a launch;
// only fp summation order varies run-to-run (well inside 1e-3 tolerance).
__global__ void scatter_kernel(const int* __restrict__ row, const int* __restrict__ col,
                               const float* __restrict__ dinv,
                               int* __restrict__ cur, int* __restrict__ cidx,
                               float* __restrict__ cw, int E)
{
    int e = blockIdx.x * blockDim.x + threadIdx.x;
    if (e < E) {
        int r = row[e], c = col[e];
        if (r != c) {
            int pos = atomicAdd(&cur[r], 1);
            cidx[pos] = c;
            cw[pos]   = -dinv[r] * dinv[c];
        }
    }
}

// Combined weight: Wc[0:128]=W0-W2, Wc[128:256]=W1, Wc[256:384]=2*W2
// (folds Tx2 = 2*prop(Tx1) - Tx0 into one K=384 GEMM)
__global__ void prep_w_kernel(const float* __restrict__ W, float* __restrict__ Wc) {
    int idx = blockIdx.x * blockDim.x + threadIdx.x;
    if (idx < D * D) {
        float w0 = W[idx];
        float w1 = W[D * D + idx];
        float w2 = W[2 * D * D + idx];
        Wc[idx]             = w0 - w2;
        Wc[D * D + idx]     = w1;
        Wc[2 * D * D + idx] = 2.f * w2;
    }
}

// ---------------- atomic-free propagation: dst[r] = sum_e w_e * src[col_e] ----------------
// One warp per destination row; each lane owns 4 contiguous features.
// Registers accumulate; single float4 store per lane. No pre-zeroing needed.
__global__ __launch_bounds__(256) void prop_csr_kernel(
    const float* __restrict__ src, float* __restrict__ dst,
    const int* __restrict__ rowptr, const int* __restrict__ cidx,
    const float* __restrict__ cw, int N)
{
    const int warp = (blockIdx.x * blockDim.x + threadIdx.x) >> 5;
    const int lane = threadIdx.x & 31;
    if (warp >= N) return;

    const int s = __ldg(rowptr + warp);
    const int e = __ldg(rowptr + warp + 1);

    float ax = 0.f, ay = 0.f, az = 0.f, aw = 0.f;
    const int off = lane * 4;

    int i = s;
    // unroll-2 for MLP (two gathers in flight per iteration)
    for (; i + 1 < e; i += 2) {
        int   c0 = __ldg(cidx + i);
        int   c1 = __ldg(cidx + i + 1);
        float w0 = __ldg(cw + i);
        float w1 = __ldg(cw + i + 1);
        float4 v0 = *reinterpret_cast<const float4*>(src + (size_t)c0 * D + off);
        float4 v1 = *reinterpret_cast<const float4*>(src + (size_t)c1 * D + off);
        ax = fmaf(w0, v0.x, ax); ay = fmaf(w0, v0.y, ay);
        az = fmaf(w0, v0.z, az); aw = fmaf(w0, v0.w, aw);
        ax = fmaf(w1, v1.x, ax); ay = fmaf(w1, v1.y, ay);
        az = fmaf(w1, v1.z, az); aw = fmaf(w1, v1.w, aw);
    }
    if (i < e) {
        int   c0 = __ldg(cidx + i);
        float w0 = __ldg(cw + i);
        float4 v0 = *reinterpret_cast<const float4*>(src + (size_t)c0 * D + off);
        ax = fmaf(w0, v0.x, ax); ay = fmaf(w0, v0.y, ay);
        az = fmaf(w0, v0.z, az); aw = fmaf(w0, v0.w, aw);
    }

    *reinterpret_cast<float4*>(dst + (size_t)warp * D + off) = make_float4(ax, ay, az, aw);
}

// ---------------- fused triple GEMM + bias + ReLU (unchanged, validated) ----------------
// OUT[n,:] = relu( H[n]@Wc[0:128] + T1[n]@Wc[128:256] + P[n]@Wc[256:384] + b )
#define BM 64
#define BN 128
#define BK 16

__global__ __launch_bounds__(256) void gemm3_kernel(
    const float* __restrict__ A0, const float* __restrict__ A1, const float* __restrict__ A2,
    const float* __restrict__ Wc, const float* __restrict__ bias,
    float* __restrict__ out, int nrows)
{
    __shared__ float As[BK][BM];   // transposed A tile
    __shared__ float Bs[BK][BN];

    const int tid  = threadIdx.x;
    const int tx   = tid & 15;        // col group (8 cols)
    const int ty   = tid >> 4;        // row group (4 rows)
    const int row0 = blockIdx.x * BM;

    const int a_row = tid >> 2;
    const int a_k   = (tid & 3) << 2;
    const int b_k = tid >> 5;
    const int b_c = (tid & 31) << 2;

    float acc[4][8];
#pragma unroll
    for (int i = 0; i < 4; i++)
#pragma unroll
        for (int j = 0; j < 8; j++) acc[i][j] = 0.f;

    const int  grow  = row0 + a_row;
    const bool valid = (grow < nrows);

    for (int kc = 0; kc < 24; ++kc) {
        const int which = kc >> 3;
        const float* A  = (which == 0) ? A0 : (which == 1) ? A1 : A2;
        const int ksrc  = (kc & 7) * BK;

        float4 av = make_float4(0.f, 0.f, 0.f, 0.f);
        if (valid)
            av = *reinterpret_cast<const float4*>(A + (size_t)grow * D + ksrc + a_k);
        As[a_k + 0][a_row] = av.x;
        As[a_k + 1][a_row] = av.y;
        As[a_k + 2][a_row] = av.z;
        As[a_k + 3][a_row] = av.w;

        const float* Wrow = Wc + (size_t)(kc * BK) * D;
        *reinterpret_cast<float4*>(&Bs[b_k][b_c]) =
            *reinterpret_cast<const float4*>(Wrow + (size_t)b_k * D + b_c);
        *reinterpret_cast<float4*>(&Bs[b_k + 8][b_c]) =
            *reinterpret_cast<const float4*>(Wrow + (size_t)(b_k + 8) * D + b_c);

        __syncthreads();

#pragma unroll
        for (int kk = 0; kk < BK; kk++) {
            float4 a  = *reinterpret_cast<const float4*>(&As[kk][ty * 4]);
            float4 b0 = *reinterpret_cast<const float4*>(&Bs[kk][tx * 8]);
            float4 b1 = *reinterpret_cast<const float4*>(&Bs[kk][tx * 8 + 4]);
            float av4[4] = {a.x, a.y, a.z, a.w};
            float bv[8]  = {b0.x, b0.y, b0.z, b0.w, b1.x, b1.y, b1.z, b1.w};
#pragma unroll
            for (int i = 0; i < 4; i++)
#pragma unroll
                for (int j = 0; j < 8; j++)
                    acc[i][j] = fmaf(av4[i], bv[j], acc[i][j]);
        }
        __syncthreads();
    }

    float b0 = bias[tx * 8 + 0], b1 = bias[tx * 8 + 1], b2 = bias[tx * 8 + 2], b3 = bias[tx * 8 + 3];
    float b4 = bias[tx * 8 + 4], b5 = bias[tx * 8 + 5], b6 = bias[tx * 8 + 6], b7 = bias[tx * 8 + 7];
#pragma unroll
    for (int i = 0; i < 4; i++) {
        int r = row0 + ty * 4 + i;
        if (r >= nrows) continue;
        float4 v0, v1;
        v0.x = fmaxf(acc[i][0] + b0, 0.f);
        v0.y = fmaxf(acc[i][1] + b1, 0.f);
        v0.z = fmaxf(acc[i][2] + b2, 0.f);
        v0.w = fmaxf(acc[i][3] + b3, 0.f);
        v1.x = fmaxf(acc[i][4] + b4, 0.f);
        v1.y = fmaxf(acc[i][5] + b5, 0.f);
        v1.z = fmaxf(acc[i][6] + b6, 0.f);
        v1.w = fmaxf(acc[i][7] + b7, 0.f);
        *reinterpret_cast<float4*>(out + (size_t)r * D + tx * 8)     = v0;
        *reinterpret_cast<float4*>(out + (size_t)r * D + tx * 8 + 4) = v1;
    }
}

// ---------------- host-side orchestration ----------------
static inline int ceil_div(int a, int b) { return (a + b - 1) / b; }

extern "C" void kernel_launch(void* const* d_in, const int* in_sizes, int n_in,
                              void* d_out, int out_size)
{
    const float* x  = (const float*)d_in[0];
    const int*   ei = (const int*)  d_in[1];
    const float* W1 = (const float*)d_in[2];
    const float* b1 = (const float*)d_in[3];
    const float* W2 = (const float*)d_in[4];
    const float* b2 = (const float*)d_in[5];
    const float* W3 = (const float*)d_in[6];
    const float* b3 = (const float*)d_in[7];
    float* out = (float*)d_out;

    const int N = in_sizes[0] / D;
    const int E = in_sizes[1] / 2;
    const int* row = ei;
    const int* col = ei + E;

    float *T1, *P, *Ha, *Hb, *Wc, *dinv, *cw;
    int *cnt, *rowptr, *cur, *cidx;
    cudaGetSymbolAddress((void**)&T1,     g_T1);
    cudaGetSymbolAddress((void**)&P,      g_P);
    cudaGetSymbolAddress((void**)&Ha,     g_Ha);
    cudaGetSymbolAddress((void**)&Hb,     g_Hb);
    cudaGetSymbolAddress((void**)&Wc,     g_Wc);
    cudaGetSymbolAddress((void**)&dinv,   g_dinv);
    cudaGetSymbolAddress((void**)&cnt,    g_cnt);
    cudaGetSymbolAddress((void**)&rowptr, g_rowptr);
    cudaGetSymbolAddress((void**)&cur,    g_cur);
    cudaGetSymbolAddress((void**)&cidx,   g_cidx);
    cudaGetSymbolAddress((void**)&cw,     g_cw);

    const int egrid = ceil_div(E, 256);
    const int ngrid = ceil_div(N, 256);
    const int pgrid = ceil_div(N * 32, 256);  // one warp per dst row
    const int ggrid = ceil_div(N, BM);

    // ---- CSR build (once; serves all 6 props) ----
    zero_int_kernel<<<ngrid, 256>>>(cnt, N);
    hist_kernel<<<egrid, 256>>>(row, col, cnt, E);
    dinv_kernel<<<ngrid, 256>>>(cnt, dinv, N);
    scan_kernel<<<1, 1024>>>(cnt, rowptr, cur, N);
    scatter_kernel<<<egrid, 256>>>(row, col, dinv, cur, cidx, cw, E);

    // ---- layer 1: in = x, out = Ha ----
    prop_csr_kernel<<<pgrid, 256>>>(x,  T1, rowptr, cidx, cw, N);
    prop_csr_kernel<<<pgrid, 256>>>(T1, P,  rowptr, cidx, cw, N);
    prep_w_kernel<<<ceil_div(D * D, 256), 256>>>(W1, Wc);
    gemm3_kernel<<<ggrid, 256>>>(x, T1, P, Wc, b1, Ha, N);

    // ---- layer 2: in = Ha, out = Hb ----
    prop_csr_kernel<<<pgrid, 256>>>(Ha, T1, rowptr, cidx, cw, N);
    prop_csr_kernel<<<pgrid, 256>>>(T1, P,  rowptr, cidx, cw, N);
    prep_w_kernel<<<ceil_div(D * D, 256), 256>>>(W2, Wc);
    gemm3_kernel<<<ggrid, 256>>>(Ha, T1, P, Wc, b2, Hb, N);

    // ---- layer 3: in = Hb, out = d_out ----
    prop_csr_kernel<<<pgrid, 256>>>(Hb, T1, rowptr, cidx, cw, N);
    prop_csr_kernel<<<pgrid, 256>>>(T1, P,  rowptr, cidx, cw, N);
    prep_w_kernel<<<ceil_div(D * D, 256), 256>>>(W3, Wc);
    gemm3_kernel<<<ggrid, 256>>>(Hb, T1, P, Wc, b3, out, N);
}

// round 7
// speedup vs baseline: 2.3231x; 1.5536x over previous
#include <cuda_runtime.h>
#include <cuda_bf16.h>
#include <cstdint>

// Problem constants (N=50000, E=800000, D=HID=128, K=3)
#define MAXN 50000
#define MAXE 800000
#define D 128
#define SCAN_B 256
#define MAXBLK ((MAXN + SCAN_B - 1) / SCAN_B)   // 196

// ---------------- scratch (no allocs allowed -> __device__ globals) ----------------
__device__ float g_T1[MAXN * D];     // Tx1 = prop(H)
__device__ float g_P [MAXN * D];     // P   = prop(Tx1)
__device__ float g_Ha[MAXN * D];     // layer outputs (ping)
__device__ float g_Hb[MAXN * D];     // layer outputs (pong)
__device__ float g_Wc[3 * D * D];    // combined weight [384][128]: {W0-W2, W1, 2*W2}
__device__ float g_dinv[MAXN];
__device__ int   g_cnt   [MAXN];     // per-row non-self edge count (= degree)
__device__ int   g_rowptr[MAXN + 1];
__device__ int   g_cur   [MAXN];     // scatter cursors
__device__ int   g_cidx  [MAXE];     // CSR col indices
__device__ float g_cw    [MAXE];     // CSR edge weights
__device__ int   g_bsum  [MAXBLK];   // per-block partial sums for scan

// ---------------- CSR build ----------------
__global__ void zero_int_kernel(int* __restrict__ p, int n) {
    int i = blockIdx.x * blockDim.x + threadIdx.x;
    if (i < n) p[i] = 0;
}

__global__ void hist_kernel(const int* __restrict__ row, const int* __restrict__ col,
                            int* __restrict__ cnt, int E) {
    int e = blockIdx.x * blockDim.x + threadIdx.x;
    if (e < E) {
        int r = row[e], c = col[e];
        if (r != c) atomicAdd(&cnt[r], 1);
    }
}

__global__ void dinv_kernel(const int* __restrict__ cnt, float* __restrict__ dinv, int n) {
    int i = blockIdx.x * blockDim.x + threadIdx.x;
    if (i < n) {
        int d = cnt[i];
        dinv[i] = (d > 0) ? rsqrtf((float)d) : 0.f;
    }
}

// ---- hierarchical scan: (1) block sums, (2) scan of partials, (3) block scan + offset ----
__global__ __launch_bounds__(SCAN_B) void scan_sum_kernel(
    const int* __restrict__ cnt, int* __restrict__ bsum, int N)
{
    __shared__ int wsum[SCAN_B / 32];
    int i = blockIdx.x * SCAN_B + threadIdx.x;
    int v = (i < N) ? cnt[i] : 0;
    int lane = threadIdx.x & 31, w = threadIdx.x >> 5;
#pragma unroll
    for (int o = 16; o > 0; o >>= 1) v += __shfl_down_sync(~0u, v, o);
    if (lane == 0) wsum[w] = v;
    __syncthreads();
    if (threadIdx.x == 0) {
        int s = 0;
#pragma unroll
        for (int j = 0; j < SCAN_B / 32; j++) s += wsum[j];
        bsum[blockIdx.x] = s;
    }
}

// Exclusive scan of nblk (<=256) partials, in place. One block of 256 threads.
__global__ __launch_bounds__(256) void scan_partials_kernel(int* __restrict__ bsum, int nblk)
{
    __shared__ int woff[8];
    int t = threadIdx.x;
    int v = (t < nblk) ? bsum[t] : 0;
    int lane = t & 31, w = t >> 5;
    int x = v;
#pragma unroll
    for (int o = 1; o < 32; o <<= 1) {
        int y = __shfl_up_sync(~0u, x, o);
        if (lane >= o) x += y;
    }
    if (lane == 31) woff[w] = x;
    __syncthreads();
    if (t == 0) {
        int run = 0;
#pragma unroll
        for (int j = 0; j < 8; j++) { int tmp = woff[j]; woff[j] = run; run += tmp; }
    }
    __syncthreads();
    int excl = x - v + woff[w];
    if (t < nblk) bsum[t] = excl;
}

__global__ __launch_bounds__(SCAN_B) void scan_write_kernel(
    const int* __restrict__ cnt, const int* __restrict__ bsum,
    int* __restrict__ rowptr, int* __restrict__ cur, int N)
{
    __shared__ int woff[SCAN_B / 32];
    int t = threadIdx.x;
    int i = blockIdx.x * SCAN_B + t;
    int v = (i < N) ? cnt[i] : 0;
    int lane = t & 31, w = t >> 5;
    int x = v;
#pragma unroll
    for (int o = 1; o < 32; o <<= 1) {
        int y = __shfl_up_sync(~0u, x, o);
        if (lane >= o) x += y;
    }
    if (lane == 31) woff[w] = x;
    __syncthreads();
    if (t == 0) {
        int run = 0;
#pragma unroll
        for (int j = 0; j < SCAN_B / 32; j++) { int tmp = woff[j]; woff[j] = run; run += tmp; }
    }
    __syncthreads();
    int excl = x - v + woff[w] + bsum[blockIdx.x];
    if (i < N) { rowptr[i] = excl; cur[i] = excl; }
    if (i == N - 1) rowptr[N] = excl + v;
}

// Scatter edges into CSR, fusing edge-weight computation.
__global__ void scatter_kernel(const int* __restrict__ row, const int* __restrict__ col,
                               const float* __restrict__ dinv,
                               int* __restrict__ cur, int* __restrict__ cidx,
                               float* __restrict__ cw, int E)
{
    int e = blockIdx.x * blockDim.x + threadIdx.x;
    if (e < E) {
        int r = row[e], c = col[e];
        if (r != c) {
            int pos = atomicAdd(&cur[r], 1);
            cidx[pos] = c;
            cw[pos]   = -dinv[r] * dinv[c];
        }
    }
}

// Combined weight: Wc[0:128]=W0-W2, Wc[128:256]=W1, Wc[256:384]=2*W2
__global__ void prep_w_kernel(const float* __restrict__ W, float* __restrict__ Wc) {
    int idx = blockIdx.x * blockDim.x + threadIdx.x;
    if (idx < D * D) {
        float w0 = W[idx];
        float w1 = W[D * D + idx];
        float w2 = W[2 * D * D + idx];
        Wc[idx]             = w0 - w2;
        Wc[D * D + idx]     = w1;
        Wc[2 * D * D + idx] = 2.f * w2;
    }
}

// ---------------- atomic-free propagation: dst[r] = sum_e w_e * src[col_e] ----------------
__global__ __launch_bounds__(256) void prop_csr_kernel(
    const float* __restrict__ src, float* __restrict__ dst,
    const int* __restrict__ rowptr, const int* __restrict__ cidx,
    const float* __restrict__ cw, int N)
{
    const int warp = (blockIdx.x * blockDim.x + threadIdx.x) >> 5;
    const int lane = threadIdx.x & 31;
    if (warp >= N) return;

    const int s = __ldg(rowptr + warp);
    const int e = __ldg(rowptr + warp + 1);

    float ax = 0.f, ay = 0.f, az = 0.f, aw = 0.f;
    const int off = lane * 4;

    int i = s;
    for (; i + 1 < e; i += 2) {
        int   c0 = __ldg(cidx + i);
        int   c1 = __ldg(cidx + i + 1);
        float w0 = __ldg(cw + i);
        float w1 = __ldg(cw + i + 1);
        float4 v0 = *reinterpret_cast<const float4*>(src + (size_t)c0 * D + off);
        float4 v1 = *reinterpret_cast<const float4*>(src + (size_t)c1 * D + off);
        ax = fmaf(w0, v0.x, ax); ay = fmaf(w0, v0.y, ay);
        az = fmaf(w0, v0.z, az); aw = fmaf(w0, v0.w, aw);
        ax = fmaf(w1, v1.x, ax); ay = fmaf(w1, v1.y, ay);
        az = fmaf(w1, v1.z, az); aw = fmaf(w1, v1.w, aw);
    }
    if (i < e) {
        int   c0 = __ldg(cidx + i);
        float w0 = __ldg(cw + i);
        float4 v0 = *reinterpret_cast<const float4*>(src + (size_t)c0 * D + off);
        ax = fmaf(w0, v0.x, ax); ay = fmaf(w0, v0.y, ay);
        az = fmaf(w0, v0.z, az); aw = fmaf(w0, v0.w, aw);
    }

    *reinterpret_cast<float4*>(dst + (size_t)warp * D + off) = make_float4(ax, ay, az, aw);
}

// ---------------- fused triple GEMM + bias + ReLU ----------------
// OUT[n,:] = relu( H[n]@Wc[0:128] + T1[n]@Wc[128:256] + P[n]@Wc[256:384] + b )
// 128x128 tile, 256 threads, 8x8 microtile (split rows/cols), BK=8, double-buffered.
#define BM 128
#define BN 128
#define BK 8
#define KCHUNKS 48   // 384 / BK

__global__ __launch_bounds__(256) void gemm3_kernel(
    const float* __restrict__ A0, const float* __restrict__ A1, const float* __restrict__ A2,
    const float* __restrict__ Wc, const float* __restrict__ bias,
    float* __restrict__ out, int nrows)
{
    __shared__ float As[2][BK][BM];
    __shared__ float Bs[2][BK][BN];

    const int tid  = threadIdx.x;
    const int tx   = tid & 15;        // col group
    const int ty   = tid >> 4;        // row group
    const int row0 = blockIdx.x * BM;

    // A load mapping: 128 rows x 8 k -> one float4 per thread
    const int a_row = tid >> 1;           // 0..127
    const int a_k   = (tid & 1) << 2;     // 0 or 4
    // B load mapping: 8 k x 128 cols -> one float4 per thread
    const int b_k = tid >> 5;             // 0..7
    const int b_c = (tid & 31) << 2;      // 0..124

    const int  grow  = row0 + a_row;
    const bool valid = (grow < nrows);

    float acc[8][8];
#pragma unroll
    for (int i = 0; i < 8; i++)
#pragma unroll
        for (int j = 0; j < 8; j++) acc[i][j] = 0.f;

    auto loadA = [&](int kc) -> float4 {
        const int which = kc >> 4;
        const float* A  = (which == 0) ? A0 : (which == 1) ? A1 : A2;
        const int ksrc  = (kc & 15) * BK + a_k;
        if (valid) return *reinterpret_cast<const float4*>(A + (size_t)grow * D + ksrc);
        return make_float4(0.f, 0.f, 0.f, 0.f);
    };
    auto loadB = [&](int kc) -> float4 {
        return *reinterpret_cast<const float4*>(Wc + (size_t)(kc * BK + b_k) * D + b_c);
    };

    // prologue: fill buffer 0
    {
        float4 av = loadA(0);
        float4 bv = loadB(0);
        As[0][a_k + 0][a_row] = av.x;
        As[0][a_k + 1][a_row] = av.y;
        As[0][a_k + 2][a_row] = av.z;
        As[0][a_k + 3][a_row] = av.w;
        *reinterpret_cast<float4*>(&Bs[0][b_k][b_c]) = bv;
    }
    __syncthreads();

    for (int kc = 0; kc < KCHUNKS; ++kc) {
        const int cur = kc & 1;
        float4 av2, bv2;
        if (kc + 1 < KCHUNKS) {           // prefetch next tile into registers
            av2 = loadA(kc + 1);
            bv2 = loadB(kc + 1);
        }

#pragma unroll
        for (int kk = 0; kk < BK; kk++) {
            float4 a0 = *reinterpret_cast<const float4*>(&As[cur][kk][ty * 4]);
            float4 a1 = *reinterpret_cast<const float4*>(&As[cur][kk][64 + ty * 4]);
            float4 b0 = *reinterpret_cast<const float4*>(&Bs[cur][kk][tx * 4]);
            float4 b1 = *reinterpret_cast<const float4*>(&Bs[cur][kk][64 + tx * 4]);
            float ar[8] = {a0.x, a0.y, a0.z, a0.w, a1.x, a1.y, a1.z, a1.w};
            float br[8] = {b0.x, b0.y, b0.z, b0.w, b1.x, b1.y, b1.z, b1.w};
#pragma unroll
            for (int i = 0; i < 8; i++)
#pragma unroll
                for (int j = 0; j < 8; j++)
                    acc[i][j] = fmaf(ar[i], br[j], acc[i][j]);
        }

        if (kc + 1 < KCHUNKS) {
            const int nxt = cur ^ 1;
            As[nxt][a_k + 0][a_row] = av2.x;
            As[nxt][a_k + 1][a_row] = av2.y;
            As[nxt][a_k + 2][a_row] = av2.z;
            As[nxt][a_k + 3][a_row] = av2.w;
            *reinterpret_cast<float4*>(&Bs[nxt][b_k][b_c]) = bv2;
            __syncthreads();
        }
    }

    // epilogue: + bias, ReLU, store. rows {ty*4+i, 64+ty*4+i}, cols {tx*4, 64+tx*4}
    float4 bl = *reinterpret_cast<const float4*>(bias + tx * 4);
    float4 bh = *reinterpret_cast<const float4*>(bias + 64 + tx * 4);
#pragma unroll
    for (int i = 0; i < 8; i++) {
        int r = row0 + ((i < 4) ? (ty * 4 + i) : (64 + ty * 4 + i - 4));
        if (r >= nrows) continue;
        float4 v0, v1;
        v0.x = fmaxf(acc[i][0] + bl.x, 0.f);
        v0.y = fmaxf(acc[i][1] + bl.y, 0.f);
        v0.z = fmaxf(acc[i][2] + bl.z, 0.f);
        v0.w = fmaxf(acc[i][3] + bl.w, 0.f);
        v1.x = fmaxf(acc[i][4] + bh.x, 0.f);
        v1.y = fmaxf(acc[i][5] + bh.y, 0.f);
        v1.z = fmaxf(acc[i][6] + bh.z, 0.f);
        v1.w = fmaxf(acc[i][7] + bh.w, 0.f);
        *reinterpret_cast<float4*>(out + (size_t)r * D + tx * 4)      = v0;
        *reinterpret_cast<float4*>(out + (size_t)r * D + 64 + tx * 4) = v1;
    }
}

// ---------------- host-side orchestration ----------------
static inline int ceil_div(int a, int b) { return (a + b - 1) / b; }

extern "C" void kernel_launch(void* const* d_in, const int* in_sizes, int n_in,
                              void* d_out, int out_size)
{
    const float* x  = (const float*)d_in[0];
    const int*   ei = (const int*)  d_in[1];
    const float* W1 = (const float*)d_in[2];
    const float* b1 = (const float*)d_in[3];
    const float* W2 = (const float*)d_in[4];
    const float* b2 = (const float*)d_in[5];
    const float* W3 = (const float*)d_in[6];
    const float* b3 = (const float*)d_in[7];
    float* out = (float*)d_out;

    const int N = in_sizes[0] / D;
    const int E = in_sizes[1] / 2;
    const int* row = ei;
    const int* col = ei + E;

    float *T1, *P, *Ha, *Hb, *Wc, *dinv, *cw;
    int *cnt, *rowptr, *cur, *cidx, *bsum;
    cudaGetSymbolAddress((void**)&T1,     g_T1);
    cudaGetSymbolAddress((void**)&P,      g_P);
    cudaGetSymbolAddress((void**)&Ha,     g_Ha);
    cudaGetSymbolAddress((void**)&Hb,     g_Hb);
    cudaGetSymbolAddress((void**)&Wc,     g_Wc);
    cudaGetSymbolAddress((void**)&dinv,   g_dinv);
    cudaGetSymbolAddress((void**)&cnt,    g_cnt);
    cudaGetSymbolAddress((void**)&rowptr, g_rowptr);
    cudaGetSymbolAddress((void**)&cur,    g_cur);
    cudaGetSymbolAddress((void**)&cidx,   g_cidx);
    cudaGetSymbolAddress((void**)&cw,     g_cw);
    cudaGetSymbolAddress((void**)&bsum,   g_bsum);

    const int egrid = ceil_div(E, 256);
    const int ngrid = ceil_div(N, 256);
    const int sgrid = ceil_div(N, SCAN_B);    // 196
    const int pgrid = ceil_div(N * 32, 256);  // one warp per dst row
    const int ggrid = ceil_div(N, BM);

    // ---- CSR build (once; serves all 6 props) ----
    zero_int_kernel<<<ngrid, 256>>>(cnt, N);
    hist_kernel<<<egrid, 256>>>(row, col, cnt, E);
    dinv_kernel<<<ngrid, 256>>>(cnt, dinv, N);
    scan_sum_kernel<<<sgrid, SCAN_B>>>(cnt, bsum, N);
    scan_partials_kernel<<<1, 256>>>(bsum, sgrid);
    scan_write_kernel<<<sgrid, SCAN_B>>>(cnt, bsum, rowptr, cur, N);
    scatter_kernel<<<egrid, 256>>>(row, col, dinv, cur, cidx, cw, E);

    // ---- layer 1: in = x, out = Ha ----
    prop_csr_kernel<<<pgrid, 256>>>(x,  T1, rowptr, cidx, cw, N);
    prop_csr_kernel<<<pgrid, 256>>>(T1, P,  rowptr, cidx, cw, N);
    prep_w_kernel<<<ceil_div(D * D, 256), 256>>>(W1, Wc);
    gemm3_kernel<<<ggrid, 256>>>(x, T1, P, Wc, b1, Ha, N);

    // ---- layer 2: in = Ha, out = Hb ----
    prop_csr_kernel<<<pgrid, 256>>>(Ha, T1, rowptr, cidx, cw, N);
    prop_csr_kernel<<<pgrid, 256>>>(T1, P,  rowptr, cidx, cw, N);
    prep_w_kernel<<<ceil_div(D * D, 256), 256>>>(W2, Wc);
    gemm3_kernel<<<ggrid, 256>>>(Ha, T1, P, Wc, b2, Hb, N);

    // ---- layer 3: in = Hb, out = d_out ----
    prop_csr_kernel<<<pgrid, 256>>>(Hb, T1, rowptr, cidx, cw, N);
    prop_csr_kernel<<<pgrid, 256>>>(T1, P,  rowptr, cidx, cw, N);
    prep_w_kernel<<<ceil_div(D * D, 256), 256>>>(W3, Wc);
    gemm3_kernel<<<ggrid, 256>>>(Hb, T1, P, Wc, b3, out, N);
}

// round 9
// speedup vs baseline: 2.4622x; 1.0599x over previous
#include <cuda_runtime.h>
#include <cuda_bf16.h>
#include <cstdint>

// Problem constants (N=50000, E=800000, D=HID=128, K=3)
#define MAXN 50000
#define MAXE 800000
#define D 128
#define SCAN_B 256
#define MAXBLK ((MAXN + SCAN_B - 1) / SCAN_B)   // 196

// ---------------- scratch (no allocs allowed -> __device__ globals) ----------------
__device__ float g_T1[MAXN * D];
__device__ float g_P [MAXN * D];
__device__ float g_Ha[MAXN * D];
__device__ float g_Hb[MAXN * D];
__device__ float g_Wc[3 * D * D];    // combined weight [384][128]: {W0-W2, W1, 2*W2}
__device__ float g_dinv[MAXN];
__device__ int   g_cnt   [MAXN];
__device__ int   g_rowptr[MAXN + 1];
__device__ int   g_cur   [MAXN];
__device__ int   g_cidx  [MAXE];
__device__ float g_cw    [MAXE];
__device__ int   g_bsum  [MAXBLK];

// ---------------- CSR build ----------------
__global__ void zero_int_kernel(int* __restrict__ p, int n) {
    int i = blockIdx.x * blockDim.x + threadIdx.x;
    if (i < n) p[i] = 0;
}

__global__ void hist_kernel(const int* __restrict__ row, const int* __restrict__ col,
                            int* __restrict__ cnt, int E) {
    int e = blockIdx.x * blockDim.x + threadIdx.x;
    if (e < E) {
        int r = row[e], c = col[e];
        if (r != c) atomicAdd(&cnt[r], 1);
    }
}

__global__ void dinv_kernel(const int* __restrict__ cnt, float* __restrict__ dinv, int n) {
    int i = blockIdx.x * blockDim.x + threadIdx.x;
    if (i < n) {
        int d = cnt[i];
        dinv[i] = (d > 0) ? rsqrtf((float)d) : 0.f;
    }
}

__global__ __launch_bounds__(SCAN_B) void scan_sum_kernel(
    const int* __restrict__ cnt, int* __restrict__ bsum, int N)
{
    __shared__ int wsum[SCAN_B / 32];
    int i = blockIdx.x * SCAN_B + threadIdx.x;
    int v = (i < N) ? cnt[i] : 0;
    int lane = threadIdx.x & 31, w = threadIdx.x >> 5;
#pragma unroll
    for (int o = 16; o > 0; o >>= 1) v += __shfl_down_sync(~0u, v, o);
    if (lane == 0) wsum[w] = v;
    __syncthreads();
    if (threadIdx.x == 0) {
        int s = 0;
#pragma unroll
        for (int j = 0; j < SCAN_B / 32; j++) s += wsum[j];
        bsum[blockIdx.x] = s;
    }
}

__global__ __launch_bounds__(256) void scan_partials_kernel(int* __restrict__ bsum, int nblk)
{
    __shared__ int woff[8];
    int t = threadIdx.x;
    int v = (t < nblk) ? bsum[t] : 0;
    int lane = t & 31, w = t >> 5;
    int x = v;
#pragma unroll
    for (int o = 1; o < 32; o <<= 1) {
        int y = __shfl_up_sync(~0u, x, o);
        if (lane >= o) x += y;
    }
    if (lane == 31) woff[w] = x;
    __syncthreads();
    if (t == 0) {
        int run = 0;
#pragma unroll
        for (int j = 0; j < 8; j++) { int tmp = woff[j]; woff[j] = run; run += tmp; }
    }
    __syncthreads();
    int excl = x - v + woff[w];
    if (t < nblk) bsum[t] = excl;
}

__global__ __launch_bounds__(SCAN_B) void scan_write_kernel(
    const int* __restrict__ cnt, const int* __restrict__ bsum,
    int* __restrict__ rowptr, int* __restrict__ cur, int N)
{
    __shared__ int woff[SCAN_B / 32];
    int t = threadIdx.x;
    int i = blockIdx.x * SCAN_B + t;
    int v = (i < N) ? cnt[i] : 0;
    int lane = t & 31, w = t >> 5;
    int x = v;
#pragma unroll
    for (int o = 1; o < 32; o <<= 1) {
        int y = __shfl_up_sync(~0u, x, o);
        if (lane >= o) x += y;
    }
    if (lane == 31) woff[w] = x;
    __syncthreads();
    if (t == 0) {
        int run = 0;
#pragma unroll
        for (int j = 0; j < SCAN_B / 32; j++) { int tmp = woff[j]; woff[j] = run; run += tmp; }
    }
    __syncthreads();
    int excl = x - v + woff[w] + bsum[blockIdx.x];
    if (i < N) { rowptr[i] = excl; cur[i] = excl; }
    if (i == N - 1) rowptr[N] = excl + v;
}

__global__ void scatter_kernel(const int* __restrict__ row, const int* __restrict__ col,
                               const float* __restrict__ dinv,
                               int* __restrict__ cur, int* __restrict__ cidx,
                               float* __restrict__ cw, int E)
{
    int e = blockIdx.x * blockDim.x + threadIdx.x;
    if (e < E) {
        int r = row[e], c = col[e];
        if (r != c) {
            int pos = atomicAdd(&cur[r], 1);
            cidx[pos] = c;
            cw[pos]   = -dinv[r] * dinv[c];
        }
    }
}

// Combined weight: Wc[0:128]=W0-W2, Wc[128:256]=W1, Wc[256:384]=2*W2
__global__ void prep_w_kernel(const float* __restrict__ W, float* __restrict__ Wc) {
    int idx = blockIdx.x * blockDim.x + threadIdx.x;
    if (idx < D * D) {
        float w0 = W[idx];
        float w1 = W[D * D + idx];
        float w2 = W[2 * D * D + idx];
        Wc[idx]             = w0 - w2;
        Wc[D * D + idx]     = w1;
        Wc[2 * D * D + idx] = 2.f * w2;
    }
}

// ---------------- atomic-free propagation: dst[r] = sum_e w_e * src[col_e] ----------------
__global__ __launch_bounds__(256) void prop_csr_kernel(
    const float* __restrict__ src, float* __restrict__ dst,
    const int* __restrict__ rowptr, const int* __restrict__ cidx,
    const float* __restrict__ cw, int N)
{
    const int warp = (blockIdx.x * blockDim.x + threadIdx.x) >> 5;
    const int lane = threadIdx.x & 31;
    if (warp >= N) return;

    const int s = __ldg(rowptr + warp);
    const int e = __ldg(rowptr + warp + 1);

    float ax = 0.f, ay = 0.f, az = 0.f, aw = 0.f;
    const int off = lane * 4;

    int i = s;
    for (; i + 1 < e; i += 2) {
        int   c0 = __ldg(cidx + i);
        int   c1 = __ldg(cidx + i + 1);
        float w0 = __ldg(cw + i);
        float w1 = __ldg(cw + i + 1);
        float4 v0 = *reinterpret_cast<const float4*>(src + (size_t)c0 * D + off);
        float4 v1 = *reinterpret_cast<const float4*>(src + (size_t)c1 * D + off);
        ax = fmaf(w0, v0.x, ax); ay = fmaf(w0, v0.y, ay);
        az = fmaf(w0, v0.z, az); aw = fmaf(w0, v0.w, aw);
        ax = fmaf(w1, v1.x, ax); ay = fmaf(w1, v1.y, ay);
        az = fmaf(w1, v1.z, az); aw = fmaf(w1, v1.w, aw);
    }
    if (i < e) {
        int   c0 = __ldg(cidx + i);
        float w0 = __ldg(cw + i);
        float4 v0 = *reinterpret_cast<const float4*>(src + (size_t)c0 * D + off);
        ax = fmaf(w0, v0.x, ax); ay = fmaf(w0, v0.y, ay);
        az = fmaf(w0, v0.z, az); aw = fmaf(w0, v0.w, aw);
    }

    *reinterpret_cast<float4*>(dst + (size_t)warp * D + off) = make_float4(ax, ay, az, aw);
}

// ---------------- fused triple GEMM + bias + ReLU, packed f32x2 math ----------------
// OUT[n,:] = relu( H[n]@Wc[0:128] + T1[n]@Wc[128:256] + P[n]@Wc[256:384] + b )
// 128x128 tile, 256 threads, 8x8 microtile, BK=8, double-buffered smem,
// inner product via fma.rn.f32x2 (2 exact fp32 FMA per instr — Blackwell dual fp32 pipe).
#define BM 128
#define BN 128
#define BK 8
#define KCHUNKS 48   // 384 / BK

#define FMA2(d, a, b) \
    asm("fma.rn.f32x2 %0, %1, %2, %0;" : "+l"(d) : "l"(a), "l"(b))
#define PACK_AA(d, f) \
    asm("mov.b64 %0, {%1, %1};" : "=l"(d) : "r"(__float_as_uint(f)))
#define UNPACK2(lo, hi, p) \
    asm("mov.b64 {%0, %1}, %2;" : "=r"(lo), "=r"(hi) : "l"(p))

__global__ __launch_bounds__(256) void gemm3_kernel(
    const float* __restrict__ A0, const float* __restrict__ A1, const float* __restrict__ A2,
    const float* __restrict__ Wc, const float* __restrict__ bias,
    float* __restrict__ out, int nrows)
{
    __shared__ float As[2][BK][BM];
    __shared__ float Bs[2][BK][BN];

    const int tid  = threadIdx.x;
    const int tx   = tid & 15;        // col group
    const int ty   = tid >> 4;        // row group
    const int row0 = blockIdx.x * BM;

    const int a_row = tid >> 1;           // 0..127
    const int a_k   = (tid & 1) << 2;     // 0 or 4
    const int b_k = tid >> 5;             // 0..7
    const int b_c = (tid & 31) << 2;      // 0..124

    const int  grow  = row0 + a_row;
    const bool valid = (grow < nrows);

    // packed accumulators: 8 rows x 4 column-pairs (cols {tx*4,tx*4+1,tx*4+2,tx*4+3,
    // 64+tx*4, ...} as pairs)
    unsigned long long acc2[8][4];
#pragma unroll
    for (int i = 0; i < 8; i++)
#pragma unroll
        for (int j = 0; j < 4; j++) acc2[i][j] = 0ull;

    auto loadA = [&](int kc) -> float4 {
        const int which = kc >> 4;
        const float* A  = (which == 0) ? A0 : (which == 1) ? A1 : A2;
        const int ksrc  = (kc & 15) * BK + a_k;
        if (valid) return *reinterpret_cast<const float4*>(A + (size_t)grow * D + ksrc);
        return make_float4(0.f, 0.f, 0.f, 0.f);
    };
    auto loadB = [&](int kc) -> float4 {
        return *reinterpret_cast<const float4*>(Wc + (size_t)(kc * BK + b_k) * D + b_c);
    };

    {
        float4 av = loadA(0);
        float4 bv = loadB(0);
        As[0][a_k + 0][a_row] = av.x;
        As[0][a_k + 1][a_row] = av.y;
        As[0][a_k + 2][a_row] = av.z;
        As[0][a_k + 3][a_row] = av.w;
        *reinterpret_cast<float4*>(&Bs[0][b_k][b_c]) = bv;
    }
    __syncthreads();

    for (int kc = 0; kc < KCHUNKS; ++kc) {
        const int cur = kc & 1;
        float4 av2, bv2;
        if (kc + 1 < KCHUNKS) {
            av2 = loadA(kc + 1);
            bv2 = loadB(kc + 1);
        }

#pragma unroll
        for (int kk = 0; kk < BK; kk++) {
            float4 a0 = *reinterpret_cast<const float4*>(&As[cur][kk][ty * 4]);
            float4 a1 = *reinterpret_cast<const float4*>(&As[cur][kk][64 + ty * 4]);
            // B pairs load directly as 64-bit packed (16B-aligned)
            ulonglong2 bp0 = *reinterpret_cast<const ulonglong2*>(&Bs[cur][kk][tx * 4]);
            ulonglong2 bp1 = *reinterpret_cast<const ulonglong2*>(&Bs[cur][kk][64 + tx * 4]);
            unsigned long long br[4] = {bp0.x, bp0.y, bp1.x, bp1.y};

            float ar[8] = {a0.x, a0.y, a0.z, a0.w, a1.x, a1.y, a1.z, a1.w};
            unsigned long long ar2[8];
#pragma unroll
            for (int i = 0; i < 8; i++) PACK_AA(ar2[i], ar[i]);

#pragma unroll
            for (int i = 0; i < 8; i++)
#pragma unroll
                for (int j = 0; j < 4; j++)
                    FMA2(acc2[i][j], ar2[i], br[j]);
        }

        if (kc + 1 < KCHUNKS) {
            const int nxt = cur ^ 1;
            As[nxt][a_k + 0][a_row] = av2.x;
            As[nxt][a_k + 1][a_row] = av2.y;
            As[nxt][a_k + 2][a_row] = av2.z;
            As[nxt][a_k + 3][a_row] = av2.w;
            *reinterpret_cast<float4*>(&Bs[nxt][b_k][b_c]) = bv2;
            __syncthreads();
        }
    }

    // epilogue: unpack, + bias, ReLU, store
    float4 bl = *reinterpret_cast<const float4*>(bias + tx * 4);
    float4 bh = *reinterpret_cast<const float4*>(bias + 64 + tx * 4);
    float blv[4] = {bl.x, bl.y, bl.z, bl.w};
    float bhv[4] = {bh.x, bh.y, bh.z, bh.w};
#pragma unroll
    for (int i = 0; i < 8; i++) {
        int r = row0 + ((i < 4) ? (ty * 4 + i) : (64 + ty * 4 + i - 4));
        if (r >= nrows) continue;
        float v[8];
#pragma unroll
        for (int j = 0; j < 4; j++) {
            unsigned int ulo, uhi;
            UNPACK2(ulo, uhi, acc2[i][j]);
            float base = (j < 2) ? 0.f : 0.f;
            (void)base;
            float blo = (j < 2) ? blv[j * 2]     : bhv[(j - 2) * 2];
            float bhi = (j < 2) ? blv[j * 2 + 1] : bhv[(j - 2) * 2 + 1];
            v[j * 2]     = fmaxf(__uint_as_float(ulo) + blo, 0.f);
            v[j * 2 + 1] = fmaxf(__uint_as_float(uhi) + bhi, 0.f);
        }
        *reinterpret_cast<float4*>(out + (size_t)r * D + tx * 4) =
            make_float4(v[0], v[1], v[2], v[3]);
        *reinterpret_cast<float4*>(out + (size_t)r * D + 64 + tx * 4) =
            make_float4(v[4], v[5], v[6], v[7]);
    }
}

// ---------------- host-side orchestration ----------------
static inline int ceil_div(int a, int b) { return (a + b - 1) / b; }

extern "C" void kernel_launch(void* const* d_in, const int* in_sizes, int n_in,
                              void* d_out, int out_size)
{
    const float* x  = (const float*)d_in[0];
    const int*   ei = (const int*)  d_in[1];
    const float* W1 = (const float*)d_in[2];
    const float* b1 = (const float*)d_in[3];
    const float* W2 = (const float*)d_in[4];
    const float* b2 = (const float*)d_in[5];
    const float* W3 = (const float*)d_in[6];
    const float* b3 = (const float*)d_in[7];
    float* out = (float*)d_out;

    const int N = in_sizes[0] / D;
    const int E = in_sizes[1] / 2;
    const int* row = ei;
    const int* col = ei + E;

    float *T1, *P, *Ha, *Hb, *Wc, *dinv, *cw;
    int *cnt, *rowptr, *cur, *cidx, *bsum;
    cudaGetSymbolAddress((void**)&T1,     g_T1);
    cudaGetSymbolAddress((void**)&P,      g_P);
    cudaGetSymbolAddress((void**)&Ha,     g_Ha);
    cudaGetSymbolAddress((void**)&Hb,     g_Hb);
    cudaGetSymbolAddress((void**)&Wc,     g_Wc);
    cudaGetSymbolAddress((void**)&dinv,   g_dinv);
    cudaGetSymbolAddress((void**)&cnt,    g_cnt);
    cudaGetSymbolAddress((void**)&rowptr, g_rowptr);
    cudaGetSymbolAddress((void**)&cur,    g_cur);
    cudaGetSymbolAddress((void**)&cidx,   g_cidx);
    cudaGetSymbolAddress((void**)&cw,     g_cw);
    cudaGetSymbolAddress((void**)&bsum,   g_bsum);

    const int egrid = ceil_div(E, 256);
    const int ngrid = ceil_div(N, 256);
    const int sgrid = ceil_div(N, SCAN_B);
    const int pgrid = ceil_div(N * 32, 256);
    const int ggrid = ceil_div(N, BM);

    // ---- CSR build (once; serves all 6 props) ----
    zero_int_kernel<<<ngrid, 256>>>(cnt, N);
    hist_kernel<<<egrid, 256>>>(row, col, cnt, E);
    dinv_kernel<<<ngrid, 256>>>(cnt, dinv, N);
    scan_sum_kernel<<<sgrid, SCAN_B>>>(cnt, bsum, N);
    scan_partials_kernel<<<1, 256>>>(bsum, sgrid);
    scan_write_kernel<<<sgrid, SCAN_B>>>(cnt, bsum, rowptr, cur, N);
    scatter_kernel<<<egrid, 256>>>(row, col, dinv, cur, cidx, cw, E);

    // ---- layer 1 ----
    prop_csr_kernel<<<pgrid, 256>>>(x,  T1, rowptr, cidx, cw, N);
    prop_csr_kernel<<<pgrid, 256>>>(T1, P,  rowptr, cidx, cw, N);
    prep_w_kernel<<<ceil_div(D * D, 256), 256>>>(W1, Wc);
    gemm3_kernel<<<ggrid, 256>>>(x, T1, P, Wc, b1, Ha, N);

    // ---- layer 2 ----
    prop_csr_kernel<<<pgrid, 256>>>(Ha, T1, rowptr, cidx, cw, N);
    prop_csr_kernel<<<pgrid, 256>>>(T1, P,  rowptr, cidx, cw, N);
    prep_w_kernel<<<ceil_div(D * D, 256), 256>>>(W2, Wc);
    gemm3_kernel<<<ggrid, 256>>>(Ha, T1, P, Wc, b2, Hb, N);

    // ---- layer 3 ----
    prop_csr_kernel<<<pgrid, 256>>>(Hb, T1, rowptr, cidx, cw, N);
    prop_csr_kernel<<<pgrid, 256>>>(T1, P,  rowptr, cidx, cw, N);
    prep_w_kernel<<<ceil_div(D * D, 256), 256>>>(W3, Wc);
    gemm3_kernel<<<ggrid, 256>>>(Hb, T1, P, Wc, b3, out, N);
}

// round 11
// speedup vs baseline: 2.6506x; 1.0765x over previous
#include <cuda_runtime.h>
#include <cuda_bf16.h>
#include <mma.h>
#include <cstdint>

using namespace nvcuda;

// Problem constants (N=50000, E=800000, D=HID=128, K=3)
#define MAXN 50000
#define MAXE 800000
#define D 128
#define SCAN_B 256
#define MAXBLK ((MAXN + SCAN_B - 1) / SCAN_B)   // 196

// ---------------- scratch (no allocs allowed -> __device__ globals) ----------------
__device__ float g_T1[MAXN * D];
__device__ float g_P [MAXN * D];
__device__ float g_Ha[MAXN * D];
__device__ float g_Hb[MAXN * D];
__device__ __nv_bfloat16 g_Wbhi[3 * D * D];  // combined weight [384][128], bf16 hi
__device__ __nv_bfloat16 g_Wblo[3 * D * D];  // bf16 lo (residual)
__device__ float g_dinv[MAXN];
__device__ int   g_cnt   [MAXN];
__device__ int   g_rowptr[MAXN + 1];
__device__ int   g_cur   [MAXN];
__device__ int   g_cidx  [MAXE];
__device__ float g_cw    [MAXE];
__device__ int   g_bsum  [MAXBLK];

// ---------------- CSR build (unchanged, validated) ----------------
__global__ void zero_int_kernel(int* __restrict__ p, int n) {
    int i = blockIdx.x * blockDim.x + threadIdx.x;
    if (i < n) p[i] = 0;
}

__global__ void hist_kernel(const int* __restrict__ row, const int* __restrict__ col,
                            int* __restrict__ cnt, int E) {
    int e = blockIdx.x * blockDim.x + threadIdx.x;
    if (e < E) {
        int r = row[e], c = col[e];
        if (r != c) atomicAdd(&cnt[r], 1);
    }
}

__global__ void dinv_kernel(const int* __restrict__ cnt, float* __restrict__ dinv, int n) {
    int i = blockIdx.x * blockDim.x + threadIdx.x;
    if (i < n) {
        int d = cnt[i];
        dinv[i] = (d > 0) ? rsqrtf((float)d) : 0.f;
    }
}

__global__ __launch_bounds__(SCAN_B) void scan_sum_kernel(
    const int* __restrict__ cnt, int* __restrict__ bsum, int N)
{
    __shared__ int wsum[SCAN_B / 32];
    int i = blockIdx.x * SCAN_B + threadIdx.x;
    int v = (i < N) ? cnt[i] : 0;
    int lane = threadIdx.x & 31, w = threadIdx.x >> 5;
#pragma unroll
    for (int o = 16; o > 0; o >>= 1) v += __shfl_down_sync(~0u, v, o);
    if (lane == 0) wsum[w] = v;
    __syncthreads();
    if (threadIdx.x == 0) {
        int s = 0;
#pragma unroll
        for (int j = 0; j < SCAN_B / 32; j++) s += wsum[j];
        bsum[blockIdx.x] = s;
    }
}

__global__ __launch_bounds__(256) void scan_partials_kernel(int* __restrict__ bsum, int nblk)
{
    __shared__ int woff[8];
    int t = threadIdx.x;
    int v = (t < nblk) ? bsum[t] : 0;
    int lane = t & 31, w = t >> 5;
    int x = v;
#pragma unroll
    for (int o = 1; o < 32; o <<= 1) {
        int y = __shfl_up_sync(~0u, x, o);
        if (lane >= o) x += y;
    }
    if (lane == 31) woff[w] = x;
    __syncthreads();
    if (t == 0) {
        int run = 0;
#pragma unroll
        for (int j = 0; j < 8; j++) { int tmp = woff[j]; woff[j] = run; run += tmp; }
    }
    __syncthreads();
    int excl = x - v + woff[w];
    if (t < nblk) bsum[t] = excl;
}

__global__ __launch_bounds__(SCAN_B) void scan_write_kernel(
    const int* __restrict__ cnt, const int* __restrict__ bsum,
    int* __restrict__ rowptr, int* __restrict__ cur, int N)
{
    __shared__ int woff[SCAN_B / 32];
    int t = threadIdx.x;
    int i = blockIdx.x * SCAN_B + t;
    int v = (i < N) ? cnt[i] : 0;
    int lane = t & 31, w = t >> 5;
    int x = v;
#pragma unroll
    for (int o = 1; o < 32; o <<= 1) {
        int y = __shfl_up_sync(~0u, x, o);
        if (lane >= o) x += y;
    }
    if (lane == 31) woff[w] = x;
    __syncthreads();
    if (t == 0) {
        int run = 0;
#pragma unroll
        for (int j = 0; j < SCAN_B / 32; j++) { int tmp = woff[j]; woff[j] = run; run += tmp; }
    }
    __syncthreads();
    int excl = x - v + woff[w] + bsum[blockIdx.x];
    if (i < N) { rowptr[i] = excl; cur[i] = excl; }
    if (i == N - 1) rowptr[N] = excl + v;
}

__global__ void scatter_kernel(const int* __restrict__ row, const int* __restrict__ col,
                               const float* __restrict__ dinv,
                               int* __restrict__ cur, int* __restrict__ cidx,
                               float* __restrict__ cw, int E)
{
    int e = blockIdx.x * blockDim.x + threadIdx.x;
    if (e < E) {
        int r = row[e], c = col[e];
        if (r != c) {
            int pos = atomicAdd(&cur[r], 1);
            cidx[pos] = c;
            cw[pos]   = -dinv[r] * dinv[c];
        }
    }
}

// Combined weight [gk][n], gk = p*128 + din: {W0-W2, W1, 2*W2}; split to bf16 hi/lo.
__global__ void prep_wbf_kernel(const float* __restrict__ W,
                                __nv_bfloat16* __restrict__ Bhi,
                                __nv_bfloat16* __restrict__ Blo) {
    int idx = blockIdx.x * blockDim.x + threadIdx.x;   // over 384*128
    if (idx < 3 * D * D) {
        int gk = idx / D;
        int n  = idx % D;
        int p  = gk >> 7;
        int din = gk & 127;
        float v;
        if (p == 0)      v = W[din * D + n] - W[2 * D * D + din * D + n];
        else if (p == 1) v = W[D * D + din * D + n];
        else             v = 2.f * W[2 * D * D + din * D + n];
        __nv_bfloat16 hi = __float2bfloat16(v);
        __nv_bfloat16 lo = __float2bfloat16(v - __bfloat162float(hi));
        Bhi[idx] = hi;
        Blo[idx] = lo;
    }
}

// ---------------- atomic-free propagation (unchanged, validated) ----------------
__global__ __launch_bounds__(256) void prop_csr_kernel(
    const float* __restrict__ src, float* __restrict__ dst,
    const int* __restrict__ rowptr, const int* __restrict__ cidx,
    const float* __restrict__ cw, int N)
{
    const int warp = (blockIdx.x * blockDim.x + threadIdx.x) >> 5;
    const int lane = threadIdx.x & 31;
    if (warp >= N) return;

    const int s = __ldg(rowptr + warp);
    const int e = __ldg(rowptr + warp + 1);

    float ax = 0.f, ay = 0.f, az = 0.f, aw = 0.f;
    const int off = lane * 4;

    int i = s;
    for (; i + 1 < e; i += 2) {
        int   c0 = __ldg(cidx + i);
        int   c1 = __ldg(cidx + i + 1);
        float w0 = __ldg(cw + i);
        float w1 = __ldg(cw + i + 1);
        float4 v0 = *reinterpret_cast<const float4*>(src + (size_t)c0 * D + off);
        float4 v1 = *reinterpret_cast<const float4*>(src + (size_t)c1 * D + off);
        ax = fmaf(w0, v0.x, ax); ay = fmaf(w0, v0.y, ay);
        az = fmaf(w0, v0.z, az); aw = fmaf(w0, v0.w, aw);
        ax = fmaf(w1, v1.x, ax); ay = fmaf(w1, v1.y, ay);
        az = fmaf(w1, v1.z, az); aw = fmaf(w1, v1.w, aw);
    }
    if (i < e) {
        int   c0 = __ldg(cidx + i);
        float w0 = __ldg(cw + i);
        float4 v0 = *reinterpret_cast<const float4*>(src + (size_t)c0 * D + off);
        ax = fmaf(w0, v0.x, ax); ay = fmaf(w0, v0.y, ay);
        az = fmaf(w0, v0.z, az); aw = fmaf(w0, v0.w, aw);
    }

    *reinterpret_cast<float4*>(dst + (size_t)warp * D + off) = make_float4(ax, ay, az, aw);
}

// ---------------- wmma bf16-split fused triple GEMM + bias + ReLU ----------------
// OUT[m,:] = relu( [A0|A1|A2][m,0:384] @ Wc + b )
// D = Ahi*Bhi + Ahi*Blo + Alo*Bhi in fp32 accum (2-term bf16 split, err ~2^-17).
// 128x128 CTA tile, 8 warps, each warp 32x64 via 2x4 m16n16k16 frags. K chunks of 32.
#define LDA 40            // A smem stride (bf16 elems), 80B rows (16B-mult, depadded banks)
#define LDB 136           // B smem stride
#define LDC 132           // staging stride (fp32)
#define SM_AHI  0
#define SM_ALO  (SM_AHI + 128 * LDA * 2)          // 10240
#define SM_BHI  (SM_ALO + 128 * LDA * 2)          // 20480
#define SM_BLO  (SM_BHI + 32 * LDB * 2)           // 29184
#define SM_AB_END (SM_BLO + 32 * LDB * 2)         // 37888
#define SM_STAGE_BYTES (128 * LDC * 4)            // 67584
#define SM_TOTAL (SM_STAGE_BYTES > SM_AB_END ? SM_STAGE_BYTES : SM_AB_END)

__global__ __launch_bounds__(256) void gemm3_wmma_kernel(
    const float* __restrict__ A0, const float* __restrict__ A1, const float* __restrict__ A2,
    const __nv_bfloat16* __restrict__ Whi, const __nv_bfloat16* __restrict__ Wlo,
    const float* __restrict__ bias, float* __restrict__ out, int nrows)
{
    extern __shared__ char smem[];
    __nv_bfloat16* sAhi = reinterpret_cast<__nv_bfloat16*>(smem + SM_AHI);
    __nv_bfloat16* sAlo = reinterpret_cast<__nv_bfloat16*>(smem + SM_ALO);
    __nv_bfloat16* sBhi = reinterpret_cast<__nv_bfloat16*>(smem + SM_BHI);
    __nv_bfloat16* sBlo = reinterpret_cast<__nv_bfloat16*>(smem + SM_BLO);
    float*         sC   = reinterpret_cast<float*>(smem);

    const int tid = threadIdx.x;
    const int wid = tid >> 5;
    const int wm  = wid & 3;          // warp m group: rows wm*32 .. +32
    const int wn  = wid >> 2;         // warp n group: cols wn*64 .. +64
    const int row0 = blockIdx.x * 128;

    // A-chunk load mapping: row = tid>>1 (0..127), 16 cols starting at (tid&1)*16
    const int a_row  = tid >> 1;
    const int a_c0   = (tid & 1) * 16;
    const int grow   = row0 + a_row;
    const bool valid = (grow < nrows);
    // B-chunk load mapping: row = tid>>3 (0..31), 16 cols at (tid&7)*16
    const int b_row = tid >> 3;
    const int b_c0  = (tid & 7) * 16;

    wmma::fragment<wmma::accumulator, 16, 16, 16, float> acc[2][4];
#pragma unroll
    for (int i = 0; i < 2; i++)
#pragma unroll
        for (int j = 0; j < 4; j++) wmma::fill_fragment(acc[i][j], 0.f);

    for (int ch = 0; ch < 12; ++ch) {
        const int part  = ch >> 2;
        const float* A  = (part == 0) ? A0 : (part == 1) ? A1 : A2;
        const int kbase = (ch & 3) * 32;

        // ---- A: fp32 -> bf16 hi/lo into smem ----
#pragma unroll
        for (int q = 0; q < 4; ++q) {
            const int c = a_c0 + q * 4;
            float4 v = make_float4(0.f, 0.f, 0.f, 0.f);
            if (valid)
                v = *reinterpret_cast<const float4*>(A + (size_t)grow * D + kbase + c);
            __nv_bfloat162 h01 = __floats2bfloat162_rn(v.x, v.y);
            __nv_bfloat162 h23 = __floats2bfloat162_rn(v.z, v.w);
            __nv_bfloat162 l01 = __floats2bfloat162_rn(v.x - __bfloat162float(h01.x),
                                                       v.y - __bfloat162float(h01.y));
            __nv_bfloat162 l23 = __floats2bfloat162_rn(v.z - __bfloat162float(h23.x),
                                                       v.w - __bfloat162float(h23.y));
            *reinterpret_cast<__nv_bfloat162*>(sAhi + a_row * LDA + c)     = h01;
            *reinterpret_cast<__nv_bfloat162*>(sAhi + a_row * LDA + c + 2) = h23;
            *reinterpret_cast<__nv_bfloat162*>(sAlo + a_row * LDA + c)     = l01;
            *reinterpret_cast<__nv_bfloat162*>(sAlo + a_row * LDA + c + 2) = l23;
        }
        // ---- B: precomputed bf16 hi/lo -> smem (16 bf16 = 2x 16B per thread) ----
        {
            const size_t g = (size_t)(ch * 32 + b_row) * D + b_c0;
            uint4 bh = *reinterpret_cast<const uint4*>(Whi + g);
            uint4 bl = *reinterpret_cast<const uint4*>(Wlo + g);
            uint4 bh2 = *reinterpret_cast<const uint4*>(Whi + g + 8);
            uint4 bl2 = *reinterpret_cast<const uint4*>(Wlo + g + 8);
            *reinterpret_cast<uint4*>(sBhi + b_row * LDB + b_c0)     = bh;
            *reinterpret_cast<uint4*>(sBhi + b_row * LDB + b_c0 + 8) = bh2;
            *reinterpret_cast<uint4*>(sBlo + b_row * LDB + b_c0)     = bl;
            *reinterpret_cast<uint4*>(sBlo + b_row * LDB + b_c0 + 8) = bl2;
        }
        __syncthreads();

        // ---- compute: 2 k16 steps, 2x4 tiles, 3 split products ----
#pragma unroll
        for (int k16 = 0; k16 < 2; ++k16) {
            wmma::fragment<wmma::matrix_a, 16, 16, 16, __nv_bfloat16, wmma::row_major> fahi[2], falo[2];
            wmma::fragment<wmma::matrix_b, 16, 16, 16, __nv_bfloat16, wmma::row_major> fbhi[4], fblo[4];
#pragma unroll
            for (int i = 0; i < 2; i++) {
                const __nv_bfloat16* pa = sAhi + (wm * 32 + i * 16) * LDA + k16 * 16;
                const __nv_bfloat16* pl = sAlo + (wm * 32 + i * 16) * LDA + k16 * 16;
                wmma::load_matrix_sync(fahi[i], pa, LDA);
                wmma::load_matrix_sync(falo[i], pl, LDA);
            }
#pragma unroll
            for (int j = 0; j < 4; j++) {
                const __nv_bfloat16* pb = sBhi + (k16 * 16) * LDB + wn * 64 + j * 16;
                const __nv_bfloat16* pl = sBlo + (k16 * 16) * LDB + wn * 64 + j * 16;
                wmma::load_matrix_sync(fbhi[j], pb, LDB);
                wmma::load_matrix_sync(fblo[j], pl, LDB);
            }
#pragma unroll
            for (int i = 0; i < 2; i++)
#pragma unroll
                for (int j = 0; j < 4; j++) {
                    wmma::mma_sync(acc[i][j], fahi[i], fbhi[j], acc[i][j]);
                    wmma::mma_sync(acc[i][j], fahi[i], fblo[j], acc[i][j]);
                    wmma::mma_sync(acc[i][j], falo[i], fbhi[j], acc[i][j]);
                }
        }
        __syncthreads();
    }

    // ---- epilogue: stage to smem, then bias + ReLU + coalesced store ----
#pragma unroll
    for (int i = 0; i < 2; i++)
#pragma unroll
        for (int j = 0; j < 4; j++)
            wmma::store_matrix_sync(sC + (wm * 32 + i * 16) * LDC + wn * 64 + j * 16,
                                    acc[i][j], LDC, wmma::mem_row_major);
    __syncthreads();

    // each thread: row = tid>>1, 64 cols at (tid&1)*64
    {
        const int r    = row0 + (tid >> 1);
        const int c0   = (tid & 1) * 64;
        if (r < nrows) {
            const float* src = sC + (tid >> 1) * LDC + c0;
            float* dst = out + (size_t)r * D + c0;
#pragma unroll
            for (int q = 0; q < 16; ++q) {
                float4 v = *reinterpret_cast<const float4*>(src + q * 4);
                float4 bv = *reinterpret_cast<const float4*>(bias + c0 + q * 4);
                v.x = fmaxf(v.x + bv.x, 0.f);
                v.y = fmaxf(v.y + bv.y, 0.f);
                v.z = fmaxf(v.z + bv.z, 0.f);
                v.w = fmaxf(v.w + bv.w, 0.f);
                *reinterpret_cast<float4*>(dst + q * 4) = v;
            }
        }
    }
}

// ---------------- host-side orchestration ----------------
static inline int ceil_div(int a, int b) { return (a + b - 1) / b; }

extern "C" void kernel_launch(void* const* d_in, const int* in_sizes, int n_in,
                              void* d_out, int out_size)
{
    const float* x  = (const float*)d_in[0];
    const int*   ei = (const int*)  d_in[1];
    const float* W1 = (const float*)d_in[2];
    const float* b1 = (const float*)d_in[3];
    const float* W2 = (const float*)d_in[4];
    const float* b2 = (const float*)d_in[5];
    const float* W3 = (const float*)d_in[6];
    const float* b3 = (const float*)d_in[7];
    float* out = (float*)d_out;

    const int N = in_sizes[0] / D;
    const int E = in_sizes[1] / 2;
    const int* row = ei;
    const int* col = ei + E;

    float *T1, *P, *Ha, *Hb, *dinv, *cw;
    __nv_bfloat16 *Whi, *Wlo;
    int *cnt, *rowptr, *cur, *cidx, *bsum;
    cudaGetSymbolAddress((void**)&T1,     g_T1);
    cudaGetSymbolAddress((void**)&P,      g_P);
    cudaGetSymbolAddress((void**)&Ha,     g_Ha);
    cudaGetSymbolAddress((void**)&Hb,     g_Hb);
    cudaGetSymbolAddress((void**)&Whi,    g_Wbhi);
    cudaGetSymbolAddress((void**)&Wlo,    g_Wblo);
    cudaGetSymbolAddress((void**)&dinv,   g_dinv);
    cudaGetSymbolAddress((void**)&cnt,    g_cnt);
    cudaGetSymbolAddress((void**)&rowptr, g_rowptr);
    cudaGetSymbolAddress((void**)&cur,    g_cur);
    cudaGetSymbolAddress((void**)&cidx,   g_cidx);
    cudaGetSymbolAddress((void**)&cw,     g_cw);
    cudaGetSymbolAddress((void**)&bsum,   g_bsum);

    cudaFuncSetAttribute(gemm3_wmma_kernel,
                         cudaFuncAttributeMaxDynamicSharedMemorySize, SM_TOTAL);

    const int egrid = ceil_div(E, 256);
    const int ngrid = ceil_div(N, 256);
    const int sgrid = ceil_div(N, SCAN_B);
    const int pgrid = ceil_div(N * 32, 256);
    const int ggrid = ceil_div(N, 128);
    const int wgrid = ceil_div(3 * D * D, 256);

    // ---- CSR build (once; serves all 6 props) ----
    zero_int_kernel<<<ngrid, 256>>>(cnt, N);
    hist_kernel<<<egrid, 256>>>(row, col, cnt, E);
    dinv_kernel<<<ngrid, 256>>>(cnt, dinv, N);
    scan_sum_kernel<<<sgrid, SCAN_B>>>(cnt, bsum, N);
    scan_partials_kernel<<<1, 256>>>(bsum, sgrid);
    scan_write_kernel<<<sgrid, SCAN_B>>>(cnt, bsum, rowptr, cur, N);
    scatter_kernel<<<egrid, 256>>>(row, col, dinv, cur, cidx, cw, E);

    // ---- layer 1 ----
    prop_csr_kernel<<<pgrid, 256>>>(x,  T1, rowptr, cidx, cw, N);
    prop_csr_kernel<<<pgrid, 256>>>(T1, P,  rowptr, cidx, cw, N);
    prep_wbf_kernel<<<wgrid, 256>>>(W1, Whi, Wlo);
    gemm3_wmma_kernel<<<ggrid, 256, SM_TOTAL>>>(x, T1, P, Whi, Wlo, b1, Ha, N);

    // ---- layer 2 ----
    prop_csr_kernel<<<pgrid, 256>>>(Ha, T1, rowptr, cidx, cw, N);
    prop_csr_kernel<<<pgrid, 256>>>(T1, P,  rowptr, cidx, cw, N);
    prep_wbf_kernel<<<wgrid, 256>>>(W2, Whi, Wlo);
    gemm3_wmma_kernel<<<ggrid, 256, SM_TOTAL>>>(Ha, T1, P, Whi, Wlo, b2, Hb, N);

    // ---- layer 3 ----
    prop_csr_kernel<<<pgrid, 256>>>(Hb, T1, rowptr, cidx, cw, N);
    prop_csr_kernel<<<pgrid, 256>>>(T1, P,  rowptr, cidx, cw, N);
    prep_wbf_kernel<<<wgrid, 256>>>(W3, Whi, Wlo);
    gemm3_wmma_kernel<<<ggrid, 256, SM_TOTAL>>>(Hb, T1, P, Whi, Wlo, b3, out, N);
}

// round 12
// speedup vs baseline: 2.7783x; 1.0482x over previous
#include <cuda_runtime.h>
#include <cuda_bf16.h>
#include <mma.h>
#include <cstdint>

using namespace nvcuda;

// Problem constants (N=50000, E=800000, D=HID=128, K=3)
#define MAXN 50000
#define MAXE 800000
#define D 128
#define SCAN_B 256
#define MAXBLK ((MAXN + SCAN_B - 1) / SCAN_B)   // 196

// ---------------- scratch (no allocs allowed -> __device__ globals) ----------------
__device__ float g_T1[MAXN * D];
__device__ float g_P [MAXN * D];
__device__ float g_Ha[MAXN * D];
__device__ float g_Hb[MAXN * D];
__device__ __nv_bfloat16 g_Wbhi[3][3 * D * D];  // per-layer combined weight [384][128], bf16 hi
__device__ __nv_bfloat16 g_Wblo[3][3 * D * D];  // bf16 lo (residual)
__device__ float g_dinv[MAXN];
__device__ int   g_cnt   [MAXN];
__device__ int   g_rowptr[MAXN + 1];
__device__ int   g_cur   [MAXN];
__device__ int2  g_ecw   [MAXE];   // packed CSR edge: .x = col, .y = weight bits
__device__ int   g_bsum  [MAXBLK];

// ---------------- CSR build ----------------
__global__ void zero_int_kernel(int* __restrict__ p, int n) {
    int i = blockIdx.x * blockDim.x + threadIdx.x;
    if (i < n) p[i] = 0;
}

__global__ void hist_kernel(const int* __restrict__ row, const int* __restrict__ col,
                            int* __restrict__ cnt, int E) {
    int e = blockIdx.x * blockDim.x + threadIdx.x;
    if (e < E) {
        int r = row[e], c = col[e];
        if (r != c) atomicAdd(&cnt[r], 1);
    }
}

__global__ void dinv_kernel(const int* __restrict__ cnt, float* __restrict__ dinv, int n) {
    int i = blockIdx.x * blockDim.x + threadIdx.x;
    if (i < n) {
        int d = cnt[i];
        dinv[i] = (d > 0) ? rsqrtf((float)d) : 0.f;
    }
}

__global__ __launch_bounds__(SCAN_B) void scan_sum_kernel(
    const int* __restrict__ cnt, int* __restrict__ bsum, int N)
{
    __shared__ int wsum[SCAN_B / 32];
    int i = blockIdx.x * SCAN_B + threadIdx.x;
    int v = (i < N) ? cnt[i] : 0;
    int lane = threadIdx.x & 31, w = threadIdx.x >> 5;
#pragma unroll
    for (int o = 16; o > 0; o >>= 1) v += __shfl_down_sync(~0u, v, o);
    if (lane == 0) wsum[w] = v;
    __syncthreads();
    if (threadIdx.x == 0) {
        int s = 0;
#pragma unroll
        for (int j = 0; j < SCAN_B / 32; j++) s += wsum[j];
        bsum[blockIdx.x] = s;
    }
}

__global__ __launch_bounds__(256) void scan_partials_kernel(int* __restrict__ bsum, int nblk)
{
    __shared__ int woff[8];
    int t = threadIdx.x;
    int v = (t < nblk) ? bsum[t] : 0;
    int lane = t & 31, w = t >> 5;
    int x = v;
#pragma unroll
    for (int o = 1; o < 32; o <<= 1) {
        int y = __shfl_up_sync(~0u, x, o);
        if (lane >= o) x += y;
    }
    if (lane == 31) woff[w] = x;
    __syncthreads();
    if (t == 0) {
        int run = 0;
#pragma unroll
        for (int j = 0; j < 8; j++) { int tmp = woff[j]; woff[j] = run; run += tmp; }
    }
    __syncthreads();
    int excl = x - v + woff[w];
    if (t < nblk) bsum[t] = excl;
}

__global__ __launch_bounds__(SCAN_B) void scan_write_kernel(
    const int* __restrict__ cnt, const int* __restrict__ bsum,
    int* __restrict__ rowptr, int* __restrict__ cur, int N)
{
    __shared__ int woff[SCAN_B / 32];
    int t = threadIdx.x;
    int i = blockIdx.x * SCAN_B + t;
    int v = (i < N) ? cnt[i] : 0;
    int lane = t & 31, w = t >> 5;
    int x = v;
#pragma unroll
    for (int o = 1; o < 32; o <<= 1) {
        int y = __shfl_up_sync(~0u, x, o);
        if (lane >= o) x += y;
    }
    if (lane == 31) woff[w] = x;
    __syncthreads();
    if (t == 0) {
        int run = 0;
#pragma unroll
        for (int j = 0; j < SCAN_B / 32; j++) { int tmp = woff[j]; woff[j] = run; run += tmp; }
    }
    __syncthreads();
    int excl = x - v + woff[w] + bsum[blockIdx.x];
    if (i < N) { rowptr[i] = excl; cur[i] = excl; }
    if (i == N - 1) rowptr[N] = excl + v;
}

// Scatter into packed edge array (col + weight in one int2)
__global__ void scatter_kernel(const int* __restrict__ row, const int* __restrict__ col,
                               const float* __restrict__ dinv,
                               int* __restrict__ cur, int2* __restrict__ ecw, int E)
{
    int e = blockIdx.x * blockDim.x + threadIdx.x;
    if (e < E) {
        int r = row[e], c = col[e];
        if (r != c) {
            int pos = atomicAdd(&cur[r], 1);
            float w = -dinv[r] * dinv[c];
            ecw[pos] = make_int2(c, __float_as_int(w));
        }
    }
}

// Combined weight [gk][n], gk = p*128 + din: {W0-W2, W1, 2*W2}; bf16 hi/lo, all 3 layers.
__global__ void prep_wbf_all_kernel(const float* __restrict__ Wa, const float* __restrict__ Wb,
                                    const float* __restrict__ Wc,
                                    __nv_bfloat16* __restrict__ Bhi,
                                    __nv_bfloat16* __restrict__ Blo) {
    int t = blockIdx.x * blockDim.x + threadIdx.x;   // over 3 * 384*128
    if (t < 3 * 3 * D * D) {
        int layer = t / (3 * D * D);
        int idx   = t % (3 * D * D);
        const float* W = (layer == 0) ? Wa : (layer == 1) ? Wb : Wc;
        int gk = idx / D;
        int n  = idx % D;
        int p  = gk >> 7;
        int din = gk & 127;
        float v;
        if (p == 0)      v = W[din * D + n] - W[2 * D * D + din * D + n];
        else if (p == 1) v = W[D * D + din * D + n];
        else             v = 2.f * W[2 * D * D + din * D + n];
        __nv_bfloat16 hi = __float2bfloat16(v);
        __nv_bfloat16 lo = __float2bfloat16(v - __bfloat162float(hi));
        Bhi[t] = hi;
        Blo[t] = lo;
    }
}

// ---------------- atomic-free propagation: dst[r] = sum_e w_e * src[col_e] ----------------
// One warp per dst row; packed int2 edge loads; unroll-4 for MLP.
__global__ __launch_bounds__(256) void prop_csr_kernel(
    const float* __restrict__ src, float* __restrict__ dst,
    const int* __restrict__ rowptr, const int2* __restrict__ ecw, int N)
{
    const int warp = (blockIdx.x * blockDim.x + threadIdx.x) >> 5;
    const int lane = threadIdx.x & 31;
    if (warp >= N) return;

    const int s = __ldg(rowptr + warp);
    const int e = __ldg(rowptr + warp + 1);

    float ax = 0.f, ay = 0.f, az = 0.f, aw = 0.f;
    const int off = lane * 4;

    int i = s;
    for (; i + 3 < e; i += 4) {
        int2 e0 = __ldg(ecw + i);
        int2 e1 = __ldg(ecw + i + 1);
        int2 e2 = __ldg(ecw + i + 2);
        int2 e3 = __ldg(ecw + i + 3);
        float4 v0 = *reinterpret_cast<const float4*>(src + (size_t)e0.x * D + off);
        float4 v1 = *reinterpret_cast<const float4*>(src + (size_t)e1.x * D + off);
        float4 v2 = *reinterpret_cast<const float4*>(src + (size_t)e2.x * D + off);
        float4 v3 = *reinterpret_cast<const float4*>(src + (size_t)e3.x * D + off);
        float w0 = __int_as_float(e0.y), w1 = __int_as_float(e1.y);
        float w2 = __int_as_float(e2.y), w3 = __int_as_float(e3.y);
        ax = fmaf(w0, v0.x, ax); ay = fmaf(w0, v0.y, ay);
        az = fmaf(w0, v0.z, az); aw = fmaf(w0, v0.w, aw);
        ax = fmaf(w1, v1.x, ax); ay = fmaf(w1, v1.y, ay);
        az = fmaf(w1, v1.z, az); aw = fmaf(w1, v1.w, aw);
        ax = fmaf(w2, v2.x, ax); ay = fmaf(w2, v2.y, ay);
        az = fmaf(w2, v2.z, az); aw = fmaf(w2, v2.w, aw);
        ax = fmaf(w3, v3.x, ax); ay = fmaf(w3, v3.y, ay);
        az = fmaf(w3, v3.z, az); aw = fmaf(w3, v3.w, aw);
    }
    for (; i < e; ++i) {
        int2 e0 = __ldg(ecw + i);
        float w0 = __int_as_float(e0.y);
        float4 v0 = *reinterpret_cast<const float4*>(src + (size_t)e0.x * D + off);
        ax = fmaf(w0, v0.x, ax); ay = fmaf(w0, v0.y, ay);
        az = fmaf(w0, v0.z, az); aw = fmaf(w0, v0.w, aw);
    }

    *reinterpret_cast<float4*>(dst + (size_t)warp * D + off) = make_float4(ax, ay, az, aw);
}

// ---------------- wmma bf16-split fused triple GEMM + bias + ReLU (double-buffered) ----------------
// OUT[m,:] = relu( [A0|A1|A2][m,0:384] @ Wc + b )
// D = Ahi*Bhi + Ahi*Blo + Alo*Bhi in fp32 accum.
// 128x128 CTA tile, 8 warps, each 32x64 via 2x4 m16n16k16 frags, K chunks of 32,
// 2-stage smem pipeline with register prefetch, 1 sync/chunk.
#define LDA 40
#define LDB 136
#define LDC 132
#define A_BUF_B (128 * LDA * 2)               // 10240
#define B_BUF_B (32 * LDB * 2)                // 8704
#define SM_AHI(s)  ((s) * (2 * A_BUF_B + 2 * B_BUF_B))
#define SM_ALO(s)  (SM_AHI(s) + A_BUF_B)
#define SM_BHI(s)  (SM_ALO(s) + A_BUF_B)
#define SM_BLO(s)  (SM_BHI(s) + B_BUF_B)
#define SM_AB_END  (2 * (2 * A_BUF_B + 2 * B_BUF_B))   // 75776
#define SM_STAGE_BYTES (128 * LDC * 4)                 // 67584 (aliases mainloop smem)
#define SM_TOTAL (SM_AB_END > SM_STAGE_BYTES ? SM_AB_END : SM_STAGE_BYTES)

__global__ __launch_bounds__(256) void gemm3_wmma_kernel(
    const float* __restrict__ A0, const float* __restrict__ A1, const float* __restrict__ A2,
    const __nv_bfloat16* __restrict__ Whi, const __nv_bfloat16* __restrict__ Wlo,
    const float* __restrict__ bias, float* __restrict__ out, int nrows)
{
    extern __shared__ char smem[];
    float* sC = reinterpret_cast<float*>(smem);

    const int tid = threadIdx.x;
    const int wid = tid >> 5;
    const int wm  = wid & 3;
    const int wn  = wid >> 2;
    const int row0 = blockIdx.x * 128;

    const int a_row  = tid >> 1;
    const int a_c0   = (tid & 1) * 16;
    const int grow   = row0 + a_row;
    const bool valid = (grow < nrows);
    const int b_row = tid >> 3;
    const int b_c0  = (tid & 7) * 16;

    wmma::fragment<wmma::accumulator, 16, 16, 16, float> acc[2][4];
#pragma unroll
    for (int i = 0; i < 2; i++)
#pragma unroll
        for (int j = 0; j < 4; j++) wmma::fill_fragment(acc[i][j], 0.f);

    // gmem fetch of chunk ch into registers
    float4 ra[4];
    uint4  rb[4];
    auto fetch = [&](int ch) {
        const int part  = ch >> 2;
        const float* A  = (part == 0) ? A0 : (part == 1) ? A1 : A2;
        const int kbase = (ch & 3) * 32;
#pragma unroll
        for (int q = 0; q < 4; ++q) {
            ra[q] = make_float4(0.f, 0.f, 0.f, 0.f);
            if (valid)
                ra[q] = *reinterpret_cast<const float4*>(A + (size_t)grow * D + kbase + a_c0 + q * 4);
        }
        const size_t g = (size_t)(ch * 32 + b_row) * D + b_c0;
        rb[0] = *reinterpret_cast<const uint4*>(Whi + g);
        rb[1] = *reinterpret_cast<const uint4*>(Whi + g + 8);
        rb[2] = *reinterpret_cast<const uint4*>(Wlo + g);
        rb[3] = *reinterpret_cast<const uint4*>(Wlo + g + 8);
    };
    // convert + store registers into smem stage s
    auto stash = [&](int s) {
        __nv_bfloat16* sAhi = reinterpret_cast<__nv_bfloat16*>(smem + SM_AHI(s));
        __nv_bfloat16* sAlo = reinterpret_cast<__nv_bfloat16*>(smem + SM_ALO(s));
        __nv_bfloat16* sBhi = reinterpret_cast<__nv_bfloat16*>(smem + SM_BHI(s));
        __nv_bfloat16* sBlo = reinterpret_cast<__nv_bfloat16*>(smem + SM_BLO(s));
#pragma unroll
        for (int q = 0; q < 4; ++q) {
            const int c = a_c0 + q * 4;
            float4 v = ra[q];
            __nv_bfloat162 h01 = __floats2bfloat162_rn(v.x, v.y);
            __nv_bfloat162 h23 = __floats2bfloat162_rn(v.z, v.w);
            __nv_bfloat162 l01 = __floats2bfloat162_rn(v.x - __bfloat162float(h01.x),
                                                       v.y - __bfloat162float(h01.y));
            __nv_bfloat162 l23 = __floats2bfloat162_rn(v.z - __bfloat162float(h23.x),
                                                       v.w - __bfloat162float(h23.y));
            *reinterpret_cast<__nv_bfloat162*>(sAhi + a_row * LDA + c)     = h01;
            *reinterpret_cast<__nv_bfloat162*>(sAhi + a_row * LDA + c + 2) = h23;
            *reinterpret_cast<__nv_bfloat162*>(sAlo + a_row * LDA + c)     = l01;
            *reinterpret_cast<__nv_bfloat162*>(sAlo + a_row * LDA + c + 2) = l23;
        }
        *reinterpret_cast<uint4*>(sBhi + b_row * LDB + b_c0)     = rb[0];
        *reinterpret_cast<uint4*>(sBhi + b_row * LDB + b_c0 + 8) = rb[1];
        *reinterpret_cast<uint4*>(sBlo + b_row * LDB + b_c0)     = rb[2];
        *reinterpret_cast<uint4*>(sBlo + b_row * LDB + b_c0 + 8) = rb[3];
    };

    fetch(0);
    stash(0);
    __syncthreads();

    for (int ch = 0; ch < 12; ++ch) {
        const int cur = ch & 1;
        if (ch + 1 < 12) fetch(ch + 1);   // overlap gmem with mma below

        const __nv_bfloat16* sAhi = reinterpret_cast<const __nv_bfloat16*>(smem + SM_AHI(cur));
        const __nv_bfloat16* sAlo = reinterpret_cast<const __nv_bfloat16*>(smem + SM_ALO(cur));
        const __nv_bfloat16* sBhi = reinterpret_cast<const __nv_bfloat16*>(smem + SM_BHI(cur));
        const __nv_bfloat16* sBlo = reinterpret_cast<const __nv_bfloat16*>(smem + SM_BLO(cur));

#pragma unroll
        for (int k16 = 0; k16 < 2; ++k16) {
            wmma::fragment<wmma::matrix_a, 16, 16, 16, __nv_bfloat16, wmma::row_major> fahi[2], falo[2];
            wmma::fragment<wmma::matrix_b, 16, 16, 16, __nv_bfloat16, wmma::row_major> fbhi[4], fblo[4];
#pragma unroll
            for (int i = 0; i < 2; i++) {
                wmma::load_matrix_sync(fahi[i], sAhi + (wm * 32 + i * 16) * LDA + k16 * 16, LDA);
                wmma::load_matrix_sync(falo[i], sAlo + (wm * 32 + i * 16) * LDA + k16 * 16, LDA);
            }
#pragma unroll
            for (int j = 0; j < 4; j++) {
                wmma::load_matrix_sync(fbhi[j], sBhi + (k16 * 16) * LDB + wn * 64 + j * 16, LDB);
                wmma::load_matrix_sync(fblo[j], sBlo + (k16 * 16) * LDB + wn * 64 + j * 16, LDB);
            }
#pragma unroll
            for (int i = 0; i < 2; i++)
#pragma unroll
                for (int j = 0; j < 4; j++) {
                    wmma::mma_sync(acc[i][j], fahi[i], fbhi[j], acc[i][j]);
                    wmma::mma_sync(acc[i][j], fahi[i], fblo[j], acc[i][j]);
                    wmma::mma_sync(acc[i][j], falo[i], fbhi[j], acc[i][j]);
                }
        }

        if (ch + 1 < 12) {
            stash((ch + 1) & 1);   // writes OTHER buffer; readers above used cur
            __syncthreads();       // one sync per chunk
        }
    }
    __syncthreads();   // all reads done before stage aliases the smem

    // ---- epilogue: stage to smem, then bias + ReLU + coalesced store ----
#pragma unroll
    for (int i = 0; i < 2; i++)
#pragma unroll
        for (int j = 0; j < 4; j++)
            wmma::store_matrix_sync(sC + (wm * 32 + i * 16) * LDC + wn * 64 + j * 16,
                                    acc[i][j], LDC, wmma::mem_row_major);
    __syncthreads();

    {
        const int r  = row0 + (tid >> 1);
        const int c0 = (tid & 1) * 64;
        if (r < nrows) {
            const float* src = sC + (tid >> 1) * LDC + c0;
            float* dst = out + (size_t)r * D + c0;
#pragma unroll
            for (int q = 0; q < 16; ++q) {
                float4 v = *reinterpret_cast<const float4*>(src + q * 4);
                float4 bv = *reinterpret_cast<const float4*>(bias + c0 + q * 4);
                v.x = fmaxf(v.x + bv.x, 0.f);
                v.y = fmaxf(v.y + bv.y, 0.f);
                v.z = fmaxf(v.z + bv.z, 0.f);
                v.w = fmaxf(v.w + bv.w, 0.f);
                *reinterpret_cast<float4*>(dst + q * 4) = v;
            }
        }
    }
}

// ---------------- host-side orchestration ----------------
static inline int ceil_div(int a, int b) { return (a + b - 1) / b; }

extern "C" void kernel_launch(void* const* d_in, const int* in_sizes, int n_in,
                              void* d_out, int out_size)
{
    const float* x  = (const float*)d_in[0];
    const int*   ei = (const int*)  d_in[1];
    const float* W1 = (const float*)d_in[2];
    const float* b1 = (const float*)d_in[3];
    const float* W2 = (const float*)d_in[4];
    const float* b2 = (const float*)d_in[5];
    const float* W3 = (const float*)d_in[6];
    const float* b3 = (const float*)d_in[7];
    float* out = (float*)d_out;

    const int N = in_sizes[0] / D;
    const int E = in_sizes[1] / 2;
    const int* row = ei;
    const int* col = ei + E;

    float *T1, *P, *Ha, *Hb, *dinv;
    __nv_bfloat16 (*Whi)[3 * D * D], (*Wlo)[3 * D * D];
    int *cnt, *rowptr, *cur, *bsum;
    int2* ecw;
    cudaGetSymbolAddress((void**)&T1,     g_T1);
    cudaGetSymbolAddress((void**)&P,      g_P);
    cudaGetSymbolAddress((void**)&Ha,     g_Ha);
    cudaGetSymbolAddress((void**)&Hb,     g_Hb);
    cudaGetSymbolAddress((void**)&Whi,    g_Wbhi);
    cudaGetSymbolAddress((void**)&Wlo,    g_Wblo);
    cudaGetSymbolAddress((void**)&dinv,   g_dinv);
    cudaGetSymbolAddress((void**)&cnt,    g_cnt);
    cudaGetSymbolAddress((void**)&rowptr, g_rowptr);
    cudaGetSymbolAddress((void**)&cur,    g_cur);
    cudaGetSymbolAddress((void**)&ecw,    g_ecw);
    cudaGetSymbolAddress((void**)&bsum,   g_bsum);

    cudaFuncSetAttribute(gemm3_wmma_kernel,
                         cudaFuncAttributeMaxDynamicSharedMemorySize, SM_TOTAL);

    const int egrid = ceil_div(E, 256);
    const int ngrid = ceil_div(N, 256);
    const int sgrid = ceil_div(N, SCAN_B);
    const int pgrid = ceil_div(N * 32, 256);
    const int ggrid = ceil_div(N, 128);

    // ---- weight prep (all 3 layers, independent of everything) ----
    prep_wbf_all_kernel<<<ceil_div(3 * 3 * D * D, 256), 256>>>(W1, W2, W3, Whi[0], Wlo[0]);

    // ---- CSR build (once; serves all 6 props) ----
    zero_int_kernel<<<ngrid, 256>>>(cnt, N);
    hist_kernel<<<egrid, 256>>>(row, col, cnt, E);
    dinv_kernel<<<ngrid, 256>>>(cnt, dinv, N);
    scan_sum_kernel<<<sgrid, SCAN_B>>>(cnt, bsum, N);
    scan_partials_kernel<<<1, 256>>>(bsum, sgrid);
    scan_write_kernel<<<sgrid, SCAN_B>>>(cnt, bsum, rowptr, cur, N);
    scatter_kernel<<<egrid, 256>>>(row, col, dinv, cur, ecw, E);

    // ---- layer 1 ----
    prop_csr_kernel<<<pgrid, 256>>>(x,  T1, rowptr, ecw, N);
    prop_csr_kernel<<<pgrid, 256>>>(T1, P,  rowptr, ecw, N);
    gemm3_wmma_kernel<<<ggrid, 256, SM_TOTAL>>>(x, T1, P, Whi[0], Wlo[0], b1, Ha, N);

    // ---- layer 2 ----
    prop_csr_kernel<<<pgrid, 256>>>(Ha, T1, rowptr, ecw, N);
    prop_csr_kernel<<<pgrid, 256>>>(T1, P,  rowptr, ecw, N);
    gemm3_wmma_kernel<<<ggrid, 256, SM_TOTAL>>>(Ha, T1, P, Whi[1], Wlo[1], b2, Hb, N);

    // ---- layer 3 ----
    prop_csr_kernel<<<pgrid, 256>>>(Hb, T1, rowptr, ecw, N);
    prop_csr_kernel<<<pgrid, 256>>>(T1, P,  rowptr, ecw, N);
    gemm3_wmma_kernel<<<ggrid, 256, SM_TOTAL>>>(Hb, T1, P, Whi[2], Wlo[2], b3, out, N);
}